// round 7
// baseline (speedup 1.0000x reference)
#include <cuda_runtime.h>
#include <cuda_fp16.h>
#include <cstdint>

#define T_  256
#define NN  4000
#define DM  178
#define DI  46
#define H_  64
#define DH  64
#define FF  110   // DI + H
#define G4  256   // 4*H
#define NCHUNK (T_ * 125)   // 32000 chunks of 32 rows (4000 = 125*32)
#define GRID_MLP 296

typedef unsigned long long u64;

// ---------- device scratch ----------
__device__ float g_XZ[T_ * G4];
__device__ float g_W1m[64 * 64];     // W1[:,DI:] contiguous
__device__ float g_macro1[T_ * DH];
__device__ float g_sum[T_];
__device__ float g_cnt[T_];
__device__ int   g_mask_kind;        // 0=uint8/bool, 1=int32, 2=float32
__device__ int   g_tick;             // warp work-stealing ticket (init by k_prep)
__device__ int   g_progA[8 * 32];    // 8 striped progress lines at [i*32] (init by k_prep)

// ---------- packed f32x2 helpers ----------
__device__ __forceinline__ u64 pk2(float lo, float hi) {
    u64 r; asm("mov.b64 %0, {%1, %2};" : "=l"(r) : "f"(lo), "f"(hi)); return r;
}
__device__ __forceinline__ u64 ffma2(u64 a, u64 b, u64 c) {
    u64 d; asm("fma.rn.f32x2 %0, %1, %2, %3;" : "=l"(d) : "l"(a), "l"(b), "l"(c)); return d;
}
__device__ __forceinline__ float2 up2(u64 a) {
    float2 f; asm("mov.b64 {%0, %1}, %2;" : "=f"(f.x), "=f"(f.y) : "l"(a)); return f;
}

// ---------- activations ----------
__device__ __forceinline__ float sigm(float x) {
    float e = exp2f(-1.44269504088896340736f * x);
    return __fdividef(1.0f, 1.0f + e);
}
__device__ __forceinline__ float tanh_(float x) {
    float a = fabsf(x);
    float e = exp2f(-2.88539008177792681472f * a);
    float r = __fdividef(1.0f - e, 1.0f + e);
    return copysignf(r, x);
}

// ---------- warp MMA helpers ----------
__device__ __forceinline__ uint32_t smem_u32(const void* p) {
    uint32_t a;
    asm("{ .reg .u64 t; cvta.to.shared.u64 t, %1; cvt.u32.u64 %0, t; }" : "=r"(a) : "l"(p));
    return a;
}
__device__ __forceinline__ void ldsm4(uint32_t* r, uint32_t addr) {
    asm volatile("ldmatrix.sync.aligned.m8n8.x4.shared.b16 {%0,%1,%2,%3}, [%4];"
        : "=r"(r[0]), "=r"(r[1]), "=r"(r[2]), "=r"(r[3]) : "r"(addr));
}
__device__ __forceinline__ void mma16816(float* d, const uint32_t* a, const uint32_t* b) {
    asm volatile("mma.sync.aligned.m16n8k16.row.col.f32.f16.f16.f32 "
        "{%0,%1,%2,%3}, {%4,%5,%6,%7}, {%8,%9}, {%0,%1,%2,%3};"
        : "+f"(d[0]), "+f"(d[1]), "+f"(d[2]), "+f"(d[3])
        : "r"(a[0]), "r"(a[1]), "r"(a[2]), "r"(a[3]), "r"(b[0]), "r"(b[1]));
}
__device__ __forceinline__ uint32_t pkhf(__half a, __half b) {
    return ((uint32_t)__half_as_ushort(b) << 16) | (uint32_t)__half_as_ushort(a);
}
__device__ __forceinline__ void split_hf(float x, __half& h, __half& l) {
    h = __float2half_rn(x);
    l = __float2half_rn(x - __half2float(h));
}
// XOR SW128 swizzle: 128B rows of 64 fp16 (8 chunks of 16B)
__device__ __forceinline__ uint32_t xaddr(int r, int c) {
    return (uint32_t)(r * 128 + ((c ^ (r & 7)) << 4));
}
__device__ __forceinline__ void cp16(uint32_t saddr, const void* gaddr) {
    asm volatile("cp.async.cg.shared.global [%0], [%1], 16;" :: "r"(saddr), "l"(gaddr));
}
__device__ __forceinline__ int ld_acq(const int* p) {
    int v; asm volatile("ld.acquire.gpu.global.b32 %0, [%1];" : "=r"(v) : "l"(p)); return v;
}
__device__ __forceinline__ void st_rel(int* p, int v) {
    asm volatile("st.release.gpu.global.b32 [%0], %1;" :: "l"(p), "r"(v) : "memory");
}

// ---------- K1: XZ precompute + W1m copy + mask detect + flag init ----------
__global__ void __launch_bounds__(256) k_prep(const float* __restrict__ macro,
                                              const float* __restrict__ W_ih,
                                              const float* __restrict__ b_ih,
                                              const float* __restrict__ b_hh,
                                              const float* __restrict__ W1,
                                              const unsigned char* __restrict__ masks) {
    __shared__ float xs[DM];
    int t = blockIdx.x, g = threadIdx.x;
    if (g < DM) xs[g] = macro[t * DM + g];
    if (g == 0) { g_sum[t] = 0.f; g_cnt[t] = 0.f; }
    __syncthreads();
    float a0 = b_ih[g] + b_hh[g], a1 = 0.f, a2 = 0.f, a3 = 0.f;
    const float2* wr = (const float2*)(W_ih + g * DM);
    const float2* xs2 = (const float2*)xs;
#pragma unroll 4
    for (int j = 0; j < 88; j += 4) {
        float2 w0 = wr[j],     x0 = xs2[j];
        float2 w1 = wr[j + 1], x1 = xs2[j + 1];
        float2 w2 = wr[j + 2], x2 = xs2[j + 2];
        float2 w3 = wr[j + 3], x3 = xs2[j + 3];
        a0 = fmaf(x0.x, w0.x, fmaf(x0.y, w0.y, a0));
        a1 = fmaf(x1.x, w1.x, fmaf(x1.y, w1.y, a1));
        a2 = fmaf(x2.x, w2.x, fmaf(x2.y, w2.y, a2));
        a3 = fmaf(x3.x, w3.x, fmaf(x3.y, w3.y, a3));
    }
    { float2 w = wr[88], x = xs2[88]; a0 = fmaf(x.x, w.x, fmaf(x.y, w.y, a0)); }
    g_XZ[t * G4 + g] = (a0 + a1) + (a2 + a3);

    if (blockIdx.x == 1) {   // compact copy of W1 macro columns
        for (int idx = g; idx < 64 * 64; idx += 256) {
            int o = idx >> 6, k = idx & 63;
            g_W1m[idx] = W1[o * FF + DI + k];
        }
    }
    if (blockIdx.x == 2 && g < 9) {   // init producer/consumer state (every replay)
        if (g < 8) g_progA[g * 32] = -1;
        else g_tick = 0;
    }
    if (blockIdx.x == 0) {
        __shared__ int s_any, s_flt;
        if (g == 0) { s_any = 0; s_flt = 0; }
        __syncthreads();
        int ta = 0, tf = 0;
        for (int j = g; j < 1024; j += 256) {
            unsigned char c1 = masks[4 * j + 1], c2 = masks[4 * j + 2], c3 = masks[4 * j + 3];
            if (c1 | c2 | c3) ta = 1;
            if (c3 == 0x3F) tf = 1;
        }
        if (ta) atomicOr(&s_any, 1);
        if (tf) atomicOr(&s_flt, 1);
        __syncthreads();
        if (g == 0) g_mask_kind = s_flt ? 2 : (s_any ? 0 : 1);
    }
}

// ---------- fused MLP + producer LSTM ----------
#define SM_XHI 0            // 128 rows x 128B (per-warp 32-row regions)
#define SM_XLO 16384
#define SM_W1H 32768        // 64 x 128B each
#define SM_W1L 40960
#define SM_W2H 49152
#define SM_W2L 57344
#define SM_RAW 65536        // 8 slabs (4 warps x 2 bufs) x 5888B
#define SM_WROW 112640      // 128 floats
#define SMEM_MLP 113152

// one layer: 3-term fp16 split (ah*bh + al*bh + ah*bl); warp-local m=32
template<int KC>
__device__ __forceinline__ void do_layer(
    uint32_t sb, uint32_t aH, uint32_t aL, uint32_t bH, uint32_t bL,
    const float* iv, float acc[2][8][4],
    int wid, int a_ro, int a_co, int b_ro, int b_co)
{
#pragma unroll
    for (int mi = 0; mi < 2; mi++)
#pragma unroll
        for (int ni = 0; ni < 8; ni++) {
            acc[mi][ni][0] = iv[2 * ni];
            acc[mi][ni][1] = iv[2 * ni + 1];
            acc[mi][ni][2] = iv[2 * ni];
            acc[mi][ni][3] = iv[2 * ni + 1];
        }
#pragma unroll
    for (int kc = 0; kc < KC; kc++) {
        uint32_t ah[2][4], al[2][4], bh[4][4], bl[4][4];
#pragma unroll
        for (int mi = 0; mi < 2; mi++) {
            uint32_t off = xaddr(wid * 32 + mi * 16 + a_ro, 2 * kc + a_co);
            ldsm4(ah[mi], sb + aH + off);
            ldsm4(al[mi], sb + aL + off);
        }
#pragma unroll
        for (int np = 0; np < 4; np++) {
            uint32_t off = xaddr(np * 16 + b_ro, 2 * kc + b_co);
            ldsm4(bh[np], sb + bH + off);
            ldsm4(bl[np], sb + bL + off);
        }
#pragma unroll
        for (int mi = 0; mi < 2; mi++)
#pragma unroll
            for (int ni = 0; ni < 8; ni++)
                mma16816(acc[mi][ni], ah[mi], &bh[ni >> 1][(ni & 1) * 2]);
#pragma unroll
        for (int mi = 0; mi < 2; mi++)
#pragma unroll
            for (int ni = 0; ni < 8; ni++)
                mma16816(acc[mi][ni], al[mi], &bh[ni >> 1][(ni & 1) * 2]);
#pragma unroll
        for (int mi = 0; mi < 2; mi++)
#pragma unroll
            for (int ni = 0; ni < 8; ni++)
                mma16816(acc[mi][ni], ah[mi], &bl[ni >> 1][(ni & 1) * 2]);
    }
}

__global__ void __launch_bounds__(128, 2)
k_mlp(const float* __restrict__ indiv, const unsigned char* __restrict__ mask_raw,
      const float* __restrict__ rets,
      const float* __restrict__ W_hh, const float* __restrict__ b1,
      const float* __restrict__ W1, const float* __restrict__ W2,
      const float* __restrict__ b2, const float* __restrict__ W3,
      const float* __restrict__ b3, float* __restrict__ out_w)
{
    extern __shared__ char sm[];
    const uint32_t sb = smem_u32(sm);

    const int tid = threadIdx.x;
    const int wid = tid >> 5, lane = tid & 31;
    const int lq = lane & 7, qq = lane >> 3;
    const int a_ro = lq + ((qq & 1) << 3), a_co = qq >> 1;
    const int b_ro = lq + ((qq >> 1) << 3), b_co = qq & 1;
    const int cpair = (lane & 3) * 2;

    // ---- one-time weight staging (fp16 hi/lo, zero-pad K) ----
    for (int idx = tid; idx < 64 * 64; idx += 128) {
        int n = idx >> 6, k = idx & 63;
        float v1 = (k < DI) ? W1[n * FF + k] : 0.f;
        float v2 = W2[idx];
        uint32_t o = xaddr(n, k >> 3) + (k & 7) * 2;
        __half h, l;
        split_hf(v1, h, l);
        *(__half*)(sm + SM_W1H + o) = h;
        *(__half*)(sm + SM_W1L + o) = l;
        split_hf(v2, h, l);
        *(__half*)(sm + SM_W2H + o) = h;
        *(__half*)(sm + SM_W2L + o) = l;
    }
    float b2v[16], w3v[16];
#pragma unroll
    for (int ni = 0; ni < 8; ni++) {
        b2v[2 * ni]     = b2[ni * 8 + cpair];
        b2v[2 * ni + 1] = b2[ni * 8 + cpair + 1];
        w3v[2 * ni]     = W3[ni * 8 + cpair];
        w3v[2 * ni + 1] = W3[ni * 8 + cpair + 1];
    }
    const float b3v = b3[0];
    const int mask_kind = g_mask_kind;
    __syncthreads();

    // ================= CTA 0: LSTM producer =================
    if (blockIdx.x == 0) {
        float* h_s = (float*)(sm + SM_RAW);        // 64 floats
        float* p_s = h_s + 64;                     // 64 floats (i*g products)
        const int r0 = tid, r1 = tid + 128;        // gate rows: (i|f) and (g|o)
        u64 w0[32], w1[32];
        {
            const float4* a = (const float4*)(W_hh + r0 * H_);
            const float4* b = (const float4*)(W_hh + r1 * H_);
#pragma unroll
            for (int j = 0; j < 16; j++) {
                float4 va = a[j], vb = b[j];
                w0[2 * j] = pk2(va.x, va.y); w0[2 * j + 1] = pk2(va.z, va.w);
                w1[2 * j] = pk2(vb.x, vb.y); w1[2 * j + 1] = pk2(vb.z, vb.w);
            }
        }
        const float b1v = (tid < 64) ? b1[tid] : 0.f;
        float c = 0.f;
        if (tid < 64) h_s[tid] = 0.f;
        float z0 = g_XZ[r0], z1 = g_XZ[r1];
        __syncthreads();

        for (int t = 0; t < T_; t++) {
            u64 a00 = pk2(0.f, 0.f), a01 = a00, a10 = a00, a11 = a00;
            const float4* h4 = (const float4*)h_s;
#pragma unroll
            for (int j = 0; j < 16; j++) {
                float4 hv = h4[j];
                u64 hp0 = pk2(hv.x, hv.y), hp1 = pk2(hv.z, hv.w);
                a00 = ffma2(w0[2 * j], hp0, a00);
                a01 = ffma2(w0[2 * j + 1], hp1, a01);
                a10 = ffma2(w1[2 * j], hp0, a10);
                a11 = ffma2(w1[2 * j + 1], hp1, a11);
            }
            u64 one = pk2(1.f, 1.f);
            a00 = ffma2(one, a01, a00);
            a10 = ffma2(one, a11, a10);
            float2 s0 = up2(a00), s1 = up2(a10);
            float z0f = z0 + s0.x + s0.y;
            float z1f = z1 + s1.x + s1.y;
            if (t + 1 < T_) { z0 = g_XZ[(t + 1) * G4 + r0]; z1 = g_XZ[(t + 1) * G4 + r1]; }

            float fo0 = 0.f, fo1 = 0.f;
            if (tid < 64) {
                float iv = sigm(z0f), gv = tanh_(z1f);
                p_s[tid] = iv * gv;
            } else {
                fo0 = sigm(z0f);   // f
                fo1 = sigm(z1f);   // o
            }
            __syncthreads();       // p ready
            if (tid >= 64) {
                int j = tid - 64;
                c = fmaf(fo0, c, p_s[j]);
                h_s[j] = fo1 * tanh_(c);
            }
            __syncthreads();       // h_t ready
            // macro1[t] = b1 + W1m @ h_t
            if (tid < 64) {
                const float4* wm = (const float4*)(g_W1m + tid * 64);
                u64 m0 = pk2(b1v, 0.f), m1 = pk2(0.f, 0.f);
#pragma unroll
                for (int j = 0; j < 16; j++) {
                    float4 w = __ldg(wm + j);
                    float4 hv = h4[j];
                    m0 = ffma2(pk2(w.x, w.y), pk2(hv.x, hv.y), m0);
                    m1 = ffma2(pk2(w.z, w.w), pk2(hv.z, hv.w), m1);
                }
                m0 = ffma2(one, m1, m0);
                float2 mm = up2(m0);
                g_macro1[t * DH + tid] = mm.x + mm.y;
            }
            __syncthreads();       // macro1 stores done (CTA-visible)
            if (tid < 8) {
                __threadfence();   // release: prior stores visible at gpu scope
                st_rel(&g_progA[tid * 32], t);
            }
        }
    }

    // ================= all warps: work-stealing MLP =================
    float* wrowW = (float*)(sm + SM_WROW) + wid * 32;
    const uint32_t slab0 = sb + SM_RAW + (uint32_t)(wid * 2) * 5888;
    const int* prog_line = &g_progA[(blockIdx.x & 7) * 32];
    int seen = -1;
    float acc[2][8][4];

    auto grab = [&]() -> int {
        int c;
        if (lane == 0) c = atomicAdd(&g_tick, 1);
        return __shfl_sync(0xffffffffu, c, 0);
    };
    auto stage_issue = [&](int chunk, int buf) {
        int t = chunk / 125, p0 = (chunk % 125) * 32;
        const float4* gsrc = (const float4*)(indiv + ((size_t)t * NN + p0) * DI);
        uint32_t dst = slab0 + (uint32_t)buf * 5888;
#pragma unroll
        for (int i = lane; i < 368; i += 32)
            cp16(dst + (uint32_t)i * 16, gsrc + i);
        asm volatile("cp.async.commit_group;" ::: "memory");
    };

    int chunk = grab();
    int buf = 0;
    if (chunk < NCHUNK) stage_issue(chunk, buf);

    while (chunk < NCHUNK) {
        int nxt = grab();
        if (nxt < NCHUNK) {
            stage_issue(nxt, buf ^ 1);
            asm volatile("cp.async.wait_group 1;" ::: "memory");
        } else {
            asm volatile("cp.async.wait_group 0;" ::: "memory");
        }

        const int t = chunk / 125;
        const int p0 = (chunk % 125) * 32;
        const size_t gbase = (size_t)t * NN + p0;

        // wait until macro1[t] is published (register-cached, striped, backoff)
        if (seen < t) {
            int sl = 256;
            while ((seen = ld_acq(prog_line)) < t) {
                __nanosleep(sl);
                if (sl < 4096) sl <<= 1;
            }
        }

        float m1v[16];
#pragma unroll
        for (int ni = 0; ni < 8; ni++) {
            m1v[2 * ni]     = g_macro1[t * DH + ni * 8 + cpair];
            m1v[2 * ni + 1] = g_macro1[t * DH + ni * 8 + cpair + 1];
        }

        // split own row (lane = row) into fp16 hi/lo, swizzled
        {
            const float* rp = (const float*)(sm + SM_RAW + (wid * 2 + buf) * 5888) + lane * DI;
            const int row = wid * 32 + lane;
#pragma unroll
            for (int cch = 0; cch < 6; cch++) {
                uint32_t hw[4], lw[4];
#pragma unroll
                for (int jp = 0; jp < 4; jp++) {
                    int c0 = cch * 8 + 2 * jp, c1 = c0 + 1;
                    float x0 = (c0 < DI) ? rp[c0] : 0.f;
                    float x1 = (c1 < DI) ? rp[c1] : 0.f;
                    __half h0, l0, h1, l1;
                    split_hf(x0, h0, l0);
                    split_hf(x1, h1, l1);
                    hw[jp] = pkhf(h0, h1);
                    lw[jp] = pkhf(l0, l1);
                }
                uint32_t off = xaddr(row, cch);
                *(uint4*)(sm + SM_XHI + off) = make_uint4(hw[0], hw[1], hw[2], hw[3]);
                *(uint4*)(sm + SM_XLO + off) = make_uint4(lw[0], lw[1], lw[2], lw[3]);
            }
        }
        __syncwarp();

        // layer 1: K=48
        do_layer<3>(sb, SM_XHI, SM_XLO, SM_W1H, SM_W1L, m1v, acc,
                    wid, a_ro, a_co, b_ro, b_co);
        __syncwarp();

        // epilogue 1: relu + split, write A1 back into own rows
#pragma unroll
        for (int mi = 0; mi < 2; mi++) {
            int R0 = wid * 32 + mi * 16 + (lane >> 2);
            int R1 = R0 + 8;
#pragma unroll
            for (int ni = 0; ni < 8; ni++) {
                float a0 = fmaxf(acc[mi][ni][0], 0.f);
                float a1 = fmaxf(acc[mi][ni][1], 0.f);
                float a2 = fmaxf(acc[mi][ni][2], 0.f);
                float a3 = fmaxf(acc[mi][ni][3], 0.f);
                __half h0, l0, h1, l1, h2, l2, h3, l3;
                split_hf(a0, h0, l0); split_hf(a1, h1, l1);
                split_hf(a2, h2, l2); split_hf(a3, h3, l3);
                uint32_t off0 = xaddr(R0, ni) + (lane & 3) * 4;
                uint32_t off1 = xaddr(R1, ni) + (lane & 3) * 4;
                *(uint32_t*)(sm + SM_XHI + off0) = pkhf(h0, h1);
                *(uint32_t*)(sm + SM_XLO + off0) = pkhf(l0, l1);
                *(uint32_t*)(sm + SM_XHI + off1) = pkhf(h2, h3);
                *(uint32_t*)(sm + SM_XLO + off1) = pkhf(l2, l3);
            }
        }
        __syncwarp();

        // layer 2: K=64
        do_layer<4>(sb, SM_XHI, SM_XLO, SM_W2H, SM_W2L, b2v, acc,
                    wid, a_ro, a_co, b_ro, b_co);

        // epilogue 2: w3 dot relu -> per-row weight
        float ws[4] = {0.f, 0.f, 0.f, 0.f};
#pragma unroll
        for (int mi = 0; mi < 2; mi++)
#pragma unroll
            for (int ni = 0; ni < 8; ni++) {
                ws[2 * mi]     = fmaf(w3v[2 * ni], fmaxf(acc[mi][ni][0], 0.f),
                                 fmaf(w3v[2 * ni + 1], fmaxf(acc[mi][ni][1], 0.f), ws[2 * mi]));
                ws[2 * mi + 1] = fmaf(w3v[2 * ni], fmaxf(acc[mi][ni][2], 0.f),
                                 fmaf(w3v[2 * ni + 1], fmaxf(acc[mi][ni][3], 0.f), ws[2 * mi + 1]));
            }
#pragma unroll
        for (int i = 0; i < 4; i++) {
            ws[i] += __shfl_xor_sync(0xffffffffu, ws[i], 1);
            ws[i] += __shfl_xor_sync(0xffffffffu, ws[i], 2);
        }
        if ((lane & 3) == 0) {
            int r = lane >> 2;
            wrowW[r] = ws[0]; wrowW[r + 8] = ws[1];
            wrowW[r + 16] = ws[2]; wrowW[r + 24] = ws[3];
        }
        __syncwarp();

        // per-point finish
        float contrib, mval;
        {
            float w = wrowW[lane] + b3v;
            size_t gi = gbase + lane;
            float mf = (mask_kind == 0) ? (float)mask_raw[gi]
                     : (mask_kind == 1) ? (float)((const int*)mask_raw)[gi]
                     : ((const float*)mask_raw)[gi];
            float wm = w * mf;
            out_w[gi] = wm;
            contrib = wm * rets[gi];
            mval = mf;
        }
#pragma unroll
        for (int off = 16; off; off >>= 1) {
            contrib += __shfl_down_sync(0xffffffffu, contrib, off);
            mval    += __shfl_down_sync(0xffffffffu, mval, off);
        }
        if (lane == 0) {
            atomicAdd(&g_sum[t], contrib);
            atomicAdd(&g_cnt[t], mval);
        }
        chunk = nxt;
        buf ^= 1;
    }
}

// ---------- K5: sdf finalize ----------
__global__ void __launch_bounds__(256) k_final(float* __restrict__ out_sdf) {
    __shared__ float smr[256];
    int t = threadIdx.x;
    float cnt = g_cnt[t];
    smr[t] = cnt;
    __syncthreads();
    for (int s = 128; s > 0; s >>= 1) {
        if (t < s) smr[t] += smr[t + s];
        __syncthreads();
    }
    float mean = smr[0] * (1.0f / 256.0f);
    out_sdf[t] = g_sum[t] / cnt * mean + 1.0f;
}

// ---------- launch ----------
extern "C" void kernel_launch(void* const* d_in, const int* in_sizes, int n_in,
                              void* d_out, int out_size) {
    (void)in_sizes; (void)n_in; (void)out_size;
    const float* macro = (const float*)d_in[0];
    const float* indiv = (const float*)d_in[1];
    const unsigned char* masks = (const unsigned char*)d_in[2];
    const float* rets  = (const float*)d_in[3];
    const float* W_ih  = (const float*)d_in[4];
    const float* W_hh  = (const float*)d_in[5];
    const float* b_ih  = (const float*)d_in[6];
    const float* b_hh  = (const float*)d_in[7];
    const float* W1    = (const float*)d_in[8];
    const float* b1    = (const float*)d_in[9];
    const float* W2    = (const float*)d_in[10];
    const float* b2    = (const float*)d_in[11];
    const float* W3    = (const float*)d_in[12];
    const float* b3    = (const float*)d_in[13];

    float* out     = (float*)d_out;
    float* out_sdf = out;          // sdf [T,1]
    float* out_w   = out + T_;     // weights [1,T,N,1]

    cudaFuncSetAttribute(k_mlp, cudaFuncAttributeMaxDynamicSharedMemorySize, SMEM_MLP);

    k_prep<<<T_, G4>>>(macro, W_ih, b_ih, b_hh, W1, masks);
    k_mlp<<<GRID_MLP, 128, SMEM_MLP>>>(indiv, masks, rets, W_hh, b1,
                                       W1, W2, b2, W3, b3, out_w);
    k_final<<<1, T_>>>(out_sdf);
}

// round 8
// speedup vs baseline: 2.4166x; 2.4166x over previous
#include <cuda_runtime.h>
#include <cuda_fp16.h>
#include <cstdint>

#define T_  256
#define NN  4000
#define DM  178
#define DI  46
#define H_  64
#define DH  64
#define FF  110   // DI + H
#define G4  256   // 4*H
#define TILE 128
#define NTILES (T_ * 32)   // 8192
#define GRID_MLP 296

typedef unsigned long long u64;

// ---------- device scratch ----------
__device__ float g_XZ[T_ * G4];
__device__ float g_W1m[64 * 64];     // W1[:,DI:] contiguous
__device__ float g_macro1[T_ * DH];
__device__ float g_sum[T_];
__device__ float g_cnt[T_];
__device__ int   g_mask_kind;        // 0=uint8/bool, 1=int32, 2=float32

// ---------- packed f32x2 helpers ----------
__device__ __forceinline__ u64 pk2(float lo, float hi) {
    u64 r; asm("mov.b64 %0, {%1, %2};" : "=l"(r) : "f"(lo), "f"(hi)); return r;
}
__device__ __forceinline__ u64 ffma2(u64 a, u64 b, u64 c) {
    u64 d; asm("fma.rn.f32x2 %0, %1, %2, %3;" : "=l"(d) : "l"(a), "l"(b), "l"(c)); return d;
}
__device__ __forceinline__ float2 up2(u64 a) {
    float2 f; asm("mov.b64 {%0, %1}, %2;" : "=f"(f.x), "=f"(f.y) : "l"(a)); return f;
}

// ---------- activations ----------
__device__ __forceinline__ float sigm(float x) {
    float e = exp2f(-1.44269504088896340736f * x);
    return __fdividef(1.0f, 1.0f + e);
}
__device__ __forceinline__ float tanh_(float x) {
    float a = fabsf(x);
    float e = exp2f(-2.88539008177792681472f * a);
    float r = __fdividef(1.0f - e, 1.0f + e);
    return copysignf(r, x);
}

// ---------- warp MMA helpers ----------
__device__ __forceinline__ uint32_t smem_u32(const void* p) {
    uint32_t a;
    asm("{ .reg .u64 t; cvta.to.shared.u64 t, %1; cvt.u32.u64 %0, t; }" : "=r"(a) : "l"(p));
    return a;
}
__device__ __forceinline__ void ldsm4(uint32_t* r, uint32_t addr) {
    asm volatile("ldmatrix.sync.aligned.m8n8.x4.shared.b16 {%0,%1,%2,%3}, [%4];"
        : "=r"(r[0]), "=r"(r[1]), "=r"(r[2]), "=r"(r[3]) : "r"(addr));
}
__device__ __forceinline__ void mma16816(float* d, const uint32_t* a, const uint32_t* b) {
    asm volatile("mma.sync.aligned.m16n8k16.row.col.f32.f16.f16.f32 "
        "{%0,%1,%2,%3}, {%4,%5,%6,%7}, {%8,%9}, {%0,%1,%2,%3};"
        : "+f"(d[0]), "+f"(d[1]), "+f"(d[2]), "+f"(d[3])
        : "r"(a[0]), "r"(a[1]), "r"(a[2]), "r"(a[3]), "r"(b[0]), "r"(b[1]));
}
__device__ __forceinline__ uint32_t pkhf(__half a, __half b) {
    return ((uint32_t)__half_as_ushort(b) << 16) | (uint32_t)__half_as_ushort(a);
}
__device__ __forceinline__ void split_hf(float x, __half& h, __half& l) {
    h = __float2half_rn(x);
    l = __float2half_rn(x - __half2float(h));
}
// row/chunk -> byte offset: 144B row stride, chunk rotation mod 9
__device__ __forceinline__ uint32_t roff(int r, int c) {
    return (uint32_t)(r * 144 + ((c + (r >> 3)) % 9) * 16);
}
__device__ __forceinline__ void cp16(uint32_t saddr, const void* gaddr) {
    asm volatile("cp.async.cg.shared.global [%0], [%1], 16;" :: "r"(saddr), "l"(gaddr));
}

// ---------- K1: XZ (warp-per-gate-row, coalesced) + W1m copy + mask detect ----------
__global__ void __launch_bounds__(256) k_prep(const float* __restrict__ macro,
                                              const float* __restrict__ W_ih,
                                              const float* __restrict__ b_ih,
                                              const float* __restrict__ b_hh,
                                              const float* __restrict__ W1,
                                              const unsigned char* __restrict__ masks) {
    __shared__ float xs[DM + 14];   // padded
    int t = blockIdx.x, tid = threadIdx.x;
    if (tid < DM) xs[tid] = macro[t * DM + tid];
    else if (tid < DM + 14) xs[tid] = 0.f;
    if (tid == 0) { g_sum[t] = 0.f; g_cnt[t] = 0.f; }
    __syncthreads();
    const int wid = tid >> 5, lane = tid & 31;
    // each warp: rows g and g+8 in flight (coalesced reads)
    for (int g = wid; g < G4; g += 16) {
        const float* wr0 = W_ih + (size_t)g * DM;
        const float* wr1 = W_ih + (size_t)(g + 8) * DM;
        float s0 = 0.f, s1 = 0.f;
#pragma unroll
        for (int k = 0; k < 6; k++) {
            int j = lane + k * 32;
            float xv = xs[j];               // padded -> safe
            if (j < DM) {
                s0 = fmaf(wr0[j], xv, s0);
                s1 = fmaf(wr1[j], xv, s1);
            }
        }
#pragma unroll
        for (int o = 16; o; o >>= 1) {
            s0 += __shfl_xor_sync(0xffffffffu, s0, o);
            s1 += __shfl_xor_sync(0xffffffffu, s1, o);
        }
        if (lane == 0) {
            g_XZ[t * G4 + g]     = s0 + b_ih[g]     + b_hh[g];
            g_XZ[t * G4 + g + 8] = s1 + b_ih[g + 8] + b_hh[g + 8];
        }
    }

    if (blockIdx.x == 1) {   // compact copy of W1 macro columns
        for (int idx = tid; idx < 64 * 64; idx += 256) {
            int o = idx >> 6, k = idx & 63;
            g_W1m[idx] = W1[o * FF + DI + k];
        }
    }
    if (blockIdx.x == 0) {
        __shared__ int s_any, s_flt;
        if (tid == 0) { s_any = 0; s_flt = 0; }
        __syncthreads();
        int ta = 0, tf = 0;
        for (int j = tid; j < 1024; j += 256) {
            unsigned char c1 = masks[4 * j + 1], c2 = masks[4 * j + 2], c3 = masks[4 * j + 3];
            if (c1 | c2 | c3) ta = 1;
            if (c3 == 0x3F) tf = 1;
        }
        if (ta) atomicOr(&s_any, 1);
        if (tf) atomicOr(&s_flt, 1);
        __syncthreads();
        if (tid == 0) g_mask_kind = s_flt ? 2 : (s_any ? 0 : 1);
    }
}

// ---------- K2: LSTM scan, 128 threads, 1 sync/step, inline macro1 ----------
__global__ void __launch_bounds__(128, 1) k_lstm(const float* __restrict__ W_hh,
                                                 const float* __restrict__ b1) {
    __shared__ float h_buf[2][H_];
    const int tid = threadIdx.x;
    const int lane = tid & 31, wrp = tid >> 5;
    const int j = wrp * 16 + (lane & 15);    // hidden unit
    const int role = (lane >> 4);            // 0: i/g rows, 1: f/o rows
    const int ra = role ? (64 + j) : j;      // f : i
    const int rb = role ? (192 + j) : (128 + j);   // o : g

    // weights in registers
    u64 wa[32], wb[32];
    {
        const float4* A = (const float4*)(W_hh + (size_t)ra * H_);
        const float4* B = (const float4*)(W_hh + (size_t)rb * H_);
#pragma unroll
        for (int k = 0; k < 16; k++) {
            float4 va = A[k], vb = B[k];
            wa[2 * k] = pk2(va.x, va.y); wa[2 * k + 1] = pk2(va.z, va.w);
            wb[2 * k] = pk2(vb.x, vb.y); wb[2 * k + 1] = pk2(vb.z, vb.w);
        }
    }
    // macro1 weights: output o = tid>>1, k-half = tid&1
    const int mo = tid >> 1, mh = tid & 1;
    u64 wm[16];
    {
        const float4* M = (const float4*)(g_W1m + mo * 64 + mh * 32);
#pragma unroll
        for (int k = 0; k < 8; k++) {
            float4 v = M[k];
            wm[2 * k] = pk2(v.x, v.y); wm[2 * k + 1] = pk2(v.z, v.w);
        }
    }
    const float b1v = b1[mo];

    if (tid < 64) { h_buf[0][tid] = 0.f; h_buf[1][tid] = 0.f; }
    float c = 0.f;
    float za_c = g_XZ[ra], zb_c = g_XZ[rb];
    __syncthreads();

    const u64 one = pk2(1.f, 1.f);
    for (int t = 0; t < T_; t++) {
        const int rbuf = t & 1;
        const float4* h4 = (const float4*)h_buf[rbuf];   // h_{t-1}

        // gemv
        u64 a0 = pk2(0.f, 0.f), a1 = a0, b0 = a0, b1a = a0;
#pragma unroll
        for (int k = 0; k < 16; k++) {
            float4 hv = h4[k];
            u64 p0 = pk2(hv.x, hv.y), p1 = pk2(hv.z, hv.w);
            a0  = ffma2(wa[2 * k], p0, a0);
            a1  = ffma2(wa[2 * k + 1], p1, a1);
            b0  = ffma2(wb[2 * k], p0, b0);
            b1a = ffma2(wb[2 * k + 1], p1, b1a);
        }
        // macro1[t-1] from same h_{t-1}
        if (t > 0) {
            u64 m = pk2(0.f, 0.f);
            const float4* hm = h4 + mh * 8;
#pragma unroll
            for (int k = 0; k < 8; k++) {
                float4 hv = hm[k];
                m = ffma2(wm[2 * k], pk2(hv.x, hv.y), m);
                m = ffma2(wm[2 * k + 1], pk2(hv.z, hv.w), m);
            }
            float2 mm = up2(m);
            float ms = mm.x + mm.y;
            ms += __shfl_xor_sync(0xffffffffu, ms, 1);
            if (mh == 0) g_macro1[(t - 1) * DH + mo] = ms + b1v;
        }

        a0 = ffma2(one, a1, a0);
        b0 = ffma2(one, b1a, b0);
        float2 sa = up2(a0), sb0 = up2(b0);
        float za = za_c + sa.x + sa.y;
        float zb = zb_c + sb0.x + sb0.y;
        if (t + 1 < T_) {
            za_c = g_XZ[(t + 1) * G4 + ra];
            zb_c = g_XZ[(t + 1) * G4 + rb];
        }

        float p;   // i*g from role0
        if (role == 0) p = sigm(za) * tanh_(zb);
        else          p = 0.f;
        p = __shfl_xor_sync(0xffffffffu, p, 16);   // role1 receives role0's p
        if (role == 1) {
            float fv = sigm(za), ov = sigm(zb);
            c = fmaf(fv, c, p);
            h_buf[rbuf ^ 1][j] = ov * tanh_(c);
        }
        __syncthreads();   // h_t published
    }
    // macro1[T-1]
    {
        const float4* h4 = (const float4*)h_buf[T_ & 1];
        u64 m = pk2(0.f, 0.f);
        const float4* hm = h4 + mh * 8;
#pragma unroll
        for (int k = 0; k < 8; k++) {
            float4 hv = hm[k];
            m = ffma2(wm[2 * k], pk2(hv.x, hv.y), m);
            m = ffma2(wm[2 * k + 1], pk2(hv.z, hv.w), m);
        }
        float2 mm = up2(m);
        float ms = mm.x + mm.y;
        ms += __shfl_xor_sync(0xffffffffu, ms, 1);
        if (mh == 0) g_macro1[(T_ - 1) * DH + mo] = ms + b1v;
    }
}

// ---------- K4: warp-MMA fused MLP, per-warp independent pipelines (R5) ----------
#define SM_XHI 0
#define SM_XLO 18432
#define SM_W1H 36864
#define SM_W1L 46080
#define SM_W2H 55296
#define SM_W2L 64512
#define SM_RAW 73728      // 4 warp slabs x 5888B
#define SM_WROW (SM_RAW + 23552)
#define SMEM_MLP (SM_WROW + 512)

// one layer: 3-term fp16 split (ah*bh + al*bh + ah*bl); warp-local m=32
template<int KC>
__device__ __forceinline__ void do_layer(
    char* sm, uint32_t sb, uint32_t aH, uint32_t aL, uint32_t bH, uint32_t bL,
    const float* iv, float acc[2][8][4],
    int wid, int a_ro, int a_co, int b_ro, int b_co)
{
#pragma unroll
    for (int mi = 0; mi < 2; mi++)
#pragma unroll
        for (int ni = 0; ni < 8; ni++) {
            acc[mi][ni][0] = iv[2 * ni];
            acc[mi][ni][1] = iv[2 * ni + 1];
            acc[mi][ni][2] = iv[2 * ni];
            acc[mi][ni][3] = iv[2 * ni + 1];
        }
#pragma unroll
    for (int kc = 0; kc < KC; kc++) {
        uint32_t ah[2][4], al[2][4], bh[4][4], bl[4][4];
#pragma unroll
        for (int mi = 0; mi < 2; mi++) {
            uint32_t off = roff(wid * 32 + mi * 16 + a_ro, 2 * kc + a_co);
            ldsm4(ah[mi], sb + aH + off);
            ldsm4(al[mi], sb + aL + off);
        }
#pragma unroll
        for (int np = 0; np < 4; np++) {
            uint32_t off = roff(np * 16 + b_ro, 2 * kc + b_co);
            ldsm4(bh[np], sb + bH + off);
            ldsm4(bl[np], sb + bL + off);
        }
#pragma unroll
        for (int mi = 0; mi < 2; mi++)
#pragma unroll
            for (int ni = 0; ni < 8; ni++)
                mma16816(acc[mi][ni], ah[mi], &bh[ni >> 1][(ni & 1) * 2]);
#pragma unroll
        for (int mi = 0; mi < 2; mi++)
#pragma unroll
            for (int ni = 0; ni < 8; ni++)
                mma16816(acc[mi][ni], al[mi], &bh[ni >> 1][(ni & 1) * 2]);
#pragma unroll
        for (int mi = 0; mi < 2; mi++)
#pragma unroll
            for (int ni = 0; ni < 8; ni++)
                mma16816(acc[mi][ni], ah[mi], &bl[ni >> 1][(ni & 1) * 2]);
    }
}

__global__ void __launch_bounds__(128, 2)
k_mlp(const float* __restrict__ indiv, const unsigned char* __restrict__ mask_raw,
      const float* __restrict__ rets, const float* __restrict__ W1,
      const float* __restrict__ W2, const float* __restrict__ b2,
      const float* __restrict__ W3, const float* __restrict__ b3,
      float* __restrict__ out_w)
{
    extern __shared__ char sm[];
    const uint32_t sb = smem_u32(sm);
    float* wrow = (float*)(sm + SM_WROW);

    const int tid = threadIdx.x;
    const int wid = tid >> 5, lane = tid & 31;
    const int lq = lane & 7, qq = lane >> 3;
    const int a_ro = lq + ((qq & 1) << 3), a_co = qq >> 1;
    const int b_ro = lq + ((qq >> 1) << 3), b_co = qq & 1;
    const int cpair = (lane & 3) * 2;

    // ---- one-time weight staging (fp16 hi/lo, zero-pad K) ----
    for (int idx = tid; idx < 64 * 64; idx += 128) {
        int n = idx >> 6, k = idx & 63;
        float v1 = (k < DI) ? W1[n * FF + k] : 0.f;
        float v2 = W2[idx];
        uint32_t o = roff(n, k >> 3) + (k & 7) * 2;
        __half h, l;
        split_hf(v1, h, l);
        *(__half*)(sm + SM_W1H + o) = h;
        *(__half*)(sm + SM_W1L + o) = l;
        split_hf(v2, h, l);
        *(__half*)(sm + SM_W2H + o) = h;
        *(__half*)(sm + SM_W2L + o) = l;
    }
    float b2v[16], w3v[16];
#pragma unroll
    for (int ni = 0; ni < 8; ni++) {
        b2v[2 * ni]     = b2[ni * 8 + cpair];
        b2v[2 * ni + 1] = b2[ni * 8 + cpair + 1];
        w3v[2 * ni]     = W3[ni * 8 + cpair];
        w3v[2 * ni + 1] = W3[ni * 8 + cpair + 1];
    }
    const float b3v = b3[0];
    const int mask_kind = g_mask_kind;
    __syncthreads();

    float acc[2][8][4];
    const uint32_t slab = sb + SM_RAW + wid * 5888;
    const float* rawf = (const float*)(sm + SM_RAW + wid * 5888);

    for (int tile = blockIdx.x; tile < NTILES; tile += gridDim.x) {
        const int t = tile >> 5;
        const int p0 = (tile & 31) * TILE;
        const int pg = p0 + tid;
        const bool valid = pg < NN;
        const bool wvalid = (p0 + wid * 32) < NN;

        // ---- per-warp cp.async staging of own 32 rows ----
        if (wvalid) {
            const float4* gsrc = (const float4*)(indiv + ((size_t)t * NN + p0 + wid * 32) * DI);
#pragma unroll
            for (int i = lane; i < 368; i += 32)
                cp16(slab + (uint32_t)i * 16, gsrc + i);
            asm volatile("cp.async.commit_group;" ::: "memory");
            asm volatile("cp.async.wait_group 0;" ::: "memory");
        }
        float m1v[16];
#pragma unroll
        for (int ni = 0; ni < 8; ni++) {
            m1v[2 * ni]     = __ldg(&g_macro1[t * 64 + ni * 8 + cpair]);
            m1v[2 * ni + 1] = __ldg(&g_macro1[t * 64 + ni * 8 + cpair + 1]);
        }
        __syncwarp();

        // ---- split own row to fp16 hi/lo, swizzled STS ----
        {
            const float* rp = rawf + lane * DI;
            const uint32_t rbase = (uint32_t)(tid * 144);
            const int rot0 = tid >> 3;
#pragma unroll
            for (int c = 0; c < 6; c++) {
                uint32_t hw[4], lw[4];
#pragma unroll
                for (int jp = 0; jp < 4; jp++) {
                    int c0 = c * 8 + 2 * jp, c1 = c0 + 1;
                    float x0 = (c0 < DI) ? rp[c0] : 0.f;
                    float x1 = (c1 < DI) ? rp[c1] : 0.f;
                    __half h0, l0, h1, l1;
                    split_hf(x0, h0, l0);
                    split_hf(x1, h1, l1);
                    hw[jp] = pkhf(h0, h1);
                    lw[jp] = pkhf(l0, l1);
                }
                uint32_t off = rbase + (uint32_t)(((c + rot0) % 9) * 16);
                *(uint4*)(sm + SM_XHI + off) = make_uint4(hw[0], hw[1], hw[2], hw[3]);
                *(uint4*)(sm + SM_XLO + off) = make_uint4(lw[0], lw[1], lw[2], lw[3]);
            }
        }
        __syncwarp();

        // layer 1: K=48
        do_layer<3>(sm, sb, SM_XHI, SM_XLO, SM_W1H, SM_W1L, m1v, acc,
                    wid, a_ro, a_co, b_ro, b_co);
        __syncwarp();

        // epilogue 1: relu + split, write A1 back (own rows)
#pragma unroll
        for (int mi = 0; mi < 2; mi++) {
            int R0 = wid * 32 + mi * 16 + (lane >> 2);
            int R1 = R0 + 8;
#pragma unroll
            for (int ni = 0; ni < 8; ni++) {
                float a0 = fmaxf(acc[mi][ni][0], 0.f);
                float a1 = fmaxf(acc[mi][ni][1], 0.f);
                float a2 = fmaxf(acc[mi][ni][2], 0.f);
                float a3 = fmaxf(acc[mi][ni][3], 0.f);
                __half h0, l0, h1, l1, h2, l2, h3, l3;
                split_hf(a0, h0, l0); split_hf(a1, h1, l1);
                split_hf(a2, h2, l2); split_hf(a3, h3, l3);
                uint32_t off0 = roff(R0, ni) + (lane & 3) * 4;
                uint32_t off1 = roff(R1, ni) + (lane & 3) * 4;
                *(uint32_t*)(sm + SM_XHI + off0) = pkhf(h0, h1);
                *(uint32_t*)(sm + SM_XLO + off0) = pkhf(l0, l1);
                *(uint32_t*)(sm + SM_XHI + off1) = pkhf(h2, h3);
                *(uint32_t*)(sm + SM_XLO + off1) = pkhf(l2, l3);
            }
        }
        __syncwarp();

        // layer 2: K=64
        do_layer<4>(sm, sb, SM_XHI, SM_XLO, SM_W2H, SM_W2L, b2v, acc,
                    wid, a_ro, a_co, b_ro, b_co);

        // epilogue 2: w3 dot relu -> per-row weight
        float ws[4] = {0.f, 0.f, 0.f, 0.f};
#pragma unroll
        for (int mi = 0; mi < 2; mi++)
#pragma unroll
            for (int ni = 0; ni < 8; ni++) {
                ws[2 * mi]     = fmaf(w3v[2 * ni], fmaxf(acc[mi][ni][0], 0.f),
                                 fmaf(w3v[2 * ni + 1], fmaxf(acc[mi][ni][1], 0.f), ws[2 * mi]));
                ws[2 * mi + 1] = fmaf(w3v[2 * ni], fmaxf(acc[mi][ni][2], 0.f),
                                 fmaf(w3v[2 * ni + 1], fmaxf(acc[mi][ni][3], 0.f), ws[2 * mi + 1]));
            }
#pragma unroll
        for (int i = 0; i < 4; i++) {
            ws[i] += __shfl_xor_sync(0xffffffffu, ws[i], 1);
            ws[i] += __shfl_xor_sync(0xffffffffu, ws[i], 2);
        }
        float* wrowW = wrow + wid * 32;
        if ((lane & 3) == 0) {
            int r = lane >> 2;
            wrowW[r] = ws[0]; wrowW[r + 8] = ws[1];
            wrowW[r + 16] = ws[2]; wrowW[r + 24] = ws[3];
        }
        __syncwarp();

        // per-point finish
        float contrib = 0.f, mval = 0.f;
        {
            float w = wrowW[lane] + b3v;
            if (valid) {
                size_t gi = (size_t)t * NN + pg;
                float mf = (mask_kind == 0) ? (float)mask_raw[gi]
                         : (mask_kind == 1) ? (float)((const int*)mask_raw)[gi]
                         : ((const float*)mask_raw)[gi];
                float wm = w * mf;
                out_w[gi] = wm;
                contrib = wm * rets[gi];
                mval = mf;
            }
        }
#pragma unroll
        for (int off = 16; off; off >>= 1) {
            contrib += __shfl_down_sync(0xffffffffu, contrib, off);
            mval    += __shfl_down_sync(0xffffffffu, mval, off);
        }
        if (lane == 0) {
            atomicAdd(&g_sum[t], contrib);
            atomicAdd(&g_cnt[t], mval);
        }
    }
}

// ---------- K5: sdf finalize ----------
__global__ void __launch_bounds__(256) k_final(float* __restrict__ out_sdf) {
    __shared__ float smr[256];
    int t = threadIdx.x;
    float cnt = g_cnt[t];
    smr[t] = cnt;
    __syncthreads();
    for (int s = 128; s > 0; s >>= 1) {
        if (t < s) smr[t] += smr[t + s];
        __syncthreads();
    }
    float mean = smr[0] * (1.0f / 256.0f);
    out_sdf[t] = g_sum[t] / cnt * mean + 1.0f;
}

// ---------- launch ----------
extern "C" void kernel_launch(void* const* d_in, const int* in_sizes, int n_in,
                              void* d_out, int out_size) {
    (void)in_sizes; (void)n_in; (void)out_size;
    const float* macro = (const float*)d_in[0];
    const float* indiv = (const float*)d_in[1];
    const unsigned char* masks = (const unsigned char*)d_in[2];
    const float* rets  = (const float*)d_in[3];
    const float* W_ih  = (const float*)d_in[4];
    const float* W_hh  = (const float*)d_in[5];
    const float* b_ih  = (const float*)d_in[6];
    const float* b_hh  = (const float*)d_in[7];
    const float* W1    = (const float*)d_in[8];
    const float* b1    = (const float*)d_in[9];
    const float* W2    = (const float*)d_in[10];
    const float* b2    = (const float*)d_in[11];
    const float* W3    = (const float*)d_in[12];
    const float* b3    = (const float*)d_in[13];

    float* out     = (float*)d_out;
    float* out_sdf = out;          // sdf [T,1]
    float* out_w   = out + T_;     // weights [1,T,N,1]

    cudaFuncSetAttribute(k_mlp, cudaFuncAttributeMaxDynamicSharedMemorySize, SMEM_MLP);

    k_prep<<<T_, 256>>>(macro, W_ih, b_ih, b_hh, W1, masks);
    k_lstm<<<1, 128>>>(W_hh, b1);
    k_mlp<<<GRID_MLP, 128, SMEM_MLP>>>(indiv, masks, rets, W1, W2, b2, W3, b3, out_w);
    k_final<<<1, T_>>>(out_sdf);
}

// round 9
// speedup vs baseline: 2.6745x; 1.1067x over previous
#include <cuda_runtime.h>
#include <cuda_fp16.h>
#include <cstdint>

#define T_  256
#define NN  4000
#define DM  178
#define DI  46
#define H_  64
#define DH  64
#define FF  110   // DI + H
#define G4  256   // 4*H
#define TILE 128
#define NTILES (T_ * 32)   // 8192
#define GRID_MLP 296

typedef unsigned long long u64;

// ---------- device scratch ----------
__device__ float g_XZ[T_ * G4];
__device__ float g_hseq[T_ * H_];
__device__ float g_macro1[T_ * DH];
__device__ float g_sum[T_];
__device__ float g_cnt[T_];
__device__ int   g_mask_kind;   // 0=uint8/bool, 1=int32, 2=float32

// ---------- packed f32x2 helpers (LSTM) ----------
__device__ __forceinline__ u64 pk2(float lo, float hi) {
    u64 r; asm("mov.b64 %0, {%1, %2};" : "=l"(r) : "f"(lo), "f"(hi)); return r;
}
__device__ __forceinline__ u64 ffma2(u64 a, u64 b, u64 c) {
    u64 d; asm("fma.rn.f32x2 %0, %1, %2, %3;" : "=l"(d) : "l"(a), "l"(b), "l"(c)); return d;
}
__device__ __forceinline__ float2 up2(u64 a) {
    float2 f; asm("mov.b64 {%0, %1}, %2;" : "=f"(f.x), "=f"(f.y) : "l"(a)); return f;
}

// ---------- activations ----------
__device__ __forceinline__ float sigm(float x) {
    float e = exp2f(-1.44269504088896340736f * x);
    return __fdividef(1.0f, 1.0f + e);
}
__device__ __forceinline__ float tanh_(float x) {
    float a = fabsf(x);
    float e = exp2f(-2.88539008177792681472f * a);
    float r = __fdividef(1.0f - e, 1.0f + e);
    return copysignf(r, x);
}

// ---------- warp MMA helpers ----------
__device__ __forceinline__ uint32_t smem_u32(const void* p) {
    uint32_t a;
    asm("{ .reg .u64 t; cvta.to.shared.u64 t, %1; cvt.u32.u64 %0, t; }" : "=r"(a) : "l"(p));
    return a;
}
__device__ __forceinline__ void ldsm4(uint32_t* r, uint32_t addr) {
    asm volatile("ldmatrix.sync.aligned.m8n8.x4.shared.b16 {%0,%1,%2,%3}, [%4];"
        : "=r"(r[0]), "=r"(r[1]), "=r"(r[2]), "=r"(r[3]) : "r"(addr));
}
__device__ __forceinline__ void mma16816(float* d, const uint32_t* a, const uint32_t* b) {
    asm volatile("mma.sync.aligned.m16n8k16.row.col.f32.f16.f16.f32 "
        "{%0,%1,%2,%3}, {%4,%5,%6,%7}, {%8,%9}, {%0,%1,%2,%3};"
        : "+f"(d[0]), "+f"(d[1]), "+f"(d[2]), "+f"(d[3])
        : "r"(a[0]), "r"(a[1]), "r"(a[2]), "r"(a[3]), "r"(b[0]), "r"(b[1]));
}
__device__ __forceinline__ uint32_t pkhf(__half a, __half b) {
    return ((uint32_t)__half_as_ushort(b) << 16) | (uint32_t)__half_as_ushort(a);
}
__device__ __forceinline__ void split_hf(float x, __half& h, __half& l) {
    h = __float2half_rn(x);
    l = __float2half_rn(x - __half2float(h));
}
// row/chunk -> byte offset: 144B row stride, chunk rotation mod 9
__device__ __forceinline__ uint32_t roff(int r, int c) {
    return (uint32_t)(r * 144 + ((c + (r >> 3)) % 9) * 16);
}
__device__ __forceinline__ void cp16(uint32_t saddr, const void* gaddr) {
    asm volatile("cp.async.cg.shared.global [%0], [%1], 16;" :: "r"(saddr), "l"(gaddr));
}

// ---------- K1: XZ (warp-per-gate-row, coalesced) + mask detect + accum zero ----------
__global__ void __launch_bounds__(256) k_prep(const float* __restrict__ macro,
                                              const float* __restrict__ W_ih,
                                              const float* __restrict__ b_ih,
                                              const float* __restrict__ b_hh,
                                              const unsigned char* __restrict__ masks) {
    __shared__ float xs[DM + 14];   // padded to 192
    int t = blockIdx.x, tid = threadIdx.x;
    if (tid < DM) xs[tid] = macro[t * DM + tid];
    else if (tid < DM + 14) xs[tid] = 0.f;
    if (tid == 0) { g_sum[t] = 0.f; g_cnt[t] = 0.f; }
    __syncthreads();
    const int wid = tid >> 5, lane = tid & 31;
    for (int g = wid; g < G4; g += 16) {
        const float* wr0 = W_ih + (size_t)g * DM;
        const float* wr1 = W_ih + (size_t)(g + 8) * DM;
        float s0 = 0.f, s1 = 0.f;
#pragma unroll
        for (int k = 0; k < 6; k++) {
            int j = lane + k * 32;
            float xv = xs[j];
            if (j < DM) {
                s0 = fmaf(wr0[j], xv, s0);
                s1 = fmaf(wr1[j], xv, s1);
            }
        }
#pragma unroll
        for (int o = 16; o; o >>= 1) {
            s0 += __shfl_xor_sync(0xffffffffu, s0, o);
            s1 += __shfl_xor_sync(0xffffffffu, s1, o);
        }
        if (lane == 0) {
            g_XZ[t * G4 + g]     = s0 + b_ih[g]     + b_hh[g];
            g_XZ[t * G4 + g + 8] = s1 + b_ih[g + 8] + b_hh[g + 8];
        }
    }
    if (blockIdx.x == 0) {
        __shared__ int s_any, s_flt;
        if (tid == 0) { s_any = 0; s_flt = 0; }
        __syncthreads();
        int ta = 0, tf = 0;
        for (int j = tid; j < 1024; j += 256) {
            unsigned char c1 = masks[4 * j + 1], c2 = masks[4 * j + 2], c3 = masks[4 * j + 3];
            if (c1 | c2 | c3) ta = 1;
            if (c3 == 0x3F) tf = 1;
        }
        if (ta) atomicOr(&s_any, 1);
        if (tf) atomicOr(&s_flt, 1);
        __syncthreads();
        if (tid == 0) g_mask_kind = s_flt ? 2 : (s_any ? 0 : 1);
    }
}

// ---------- K2: sequential LSTM scan (R5 proven version) ----------
__global__ void __launch_bounds__(256) k_lstm(const float* __restrict__ W_hh) {
    __shared__ float h_s[H_];
    __shared__ float gact[G4];
    const int g = threadIdx.x;

    u64 w[32];
    {
        const float2* wr = (const float2*)(W_hh + g * H_);
#pragma unroll
        for (int j = 0; j < 32; j++) { float2 v = wr[j]; w[j] = pk2(v.x, v.y); }
    }
    float c = 0.f;
    if (g < H_) h_s[g] = 0.f;
    float zA = g_XZ[g];
    float zB = g_XZ[G4 + g];
    __syncthreads();

    auto do_step = [&](float zc, int t) {
        u64 a0 = pk2(0.f, 0.f), a1 = a0, a2 = a0, a3 = a0;
#pragma unroll
        for (int j = 0; j < 32; j += 4) {
            float2 h0 = ((const float2*)h_s)[j];
            float2 h1 = ((const float2*)h_s)[j + 1];
            float2 h2 = ((const float2*)h_s)[j + 2];
            float2 h3 = ((const float2*)h_s)[j + 3];
            a0 = ffma2(w[j],     pk2(h0.x, h0.y), a0);
            a1 = ffma2(w[j + 1], pk2(h1.x, h1.y), a1);
            a2 = ffma2(w[j + 2], pk2(h2.x, h2.y), a2);
            a3 = ffma2(w[j + 3], pk2(h3.x, h3.y), a3);
        }
        a0 = ffma2(pk2(1.f, 1.f), a1, a0);
        a2 = ffma2(pk2(1.f, 1.f), a3, a2);
        float2 s0 = up2(a0), s2 = up2(a2);
        float z = zc + ((s0.x + s0.y) + (s2.x + s2.y));
        float a = (g < 2 * H_ || g >= 3 * H_) ? sigm(z) : tanh_(z);
        gact[g] = a;
        __syncthreads();
        if (g < H_) {
            float iv = gact[g], fv = gact[H_ + g], gv = gact[2 * H_ + g], ov = gact[3 * H_ + g];
            c = fmaf(fv, c, iv * gv);
            float h = ov * tanh_(c);
            h_s[g] = h;
            g_hseq[t * H_ + g] = h;
        }
        __syncthreads();
    };

    for (int t = 0; t < T_; t += 2) {
        {
            float zc = zA;
            if (t + 2 < T_) zA = g_XZ[(t + 2) * G4 + g];
            do_step(zc, t);
        }
        {
            float zc = zB;
            if (t + 3 < T_) zB = g_XZ[(t + 3) * G4 + g];
            do_step(zc, t + 1);
        }
    }
}

// ---------- K3: macro1[t][o] = b1[o] + W1[o][DI:] @ h_t  (4 t per block) ----------
__global__ void __launch_bounds__(256) k_macro1(const float* __restrict__ W1,
                                                const float* __restrict__ b1) {
    __shared__ float Wm[64 * 65];
    __shared__ float hs[4 * 64];
    int t0 = blockIdx.x * 4;
    int tid = threadIdx.x;
    for (int idx = tid; idx < 64 * 64; idx += 256) {
        int o = idx >> 6, k = idx & 63;
        Wm[o * 65 + k] = W1[o * FF + DI + k];
    }
    hs[tid] = g_hseq[t0 * 64 + tid];
    __syncthreads();
    int o = tid & 63, ts = tid >> 6;
    const float* h = hs + ts * 64;
    const float* w = Wm + o * 65;
    float acc = b1[o];
#pragma unroll 8
    for (int k = 0; k < 64; k++) acc = fmaf(h[k], w[k], acc);
    g_macro1[(t0 + ts) * 64 + o] = acc;
}

// ---------- K4: warp-MMA fused MLP, per-warp pipelines + cross-tile cp.async prefetch ----------
#define SM_XHI 0
#define SM_XLO 18432
#define SM_W1H 36864
#define SM_W1L 46080
#define SM_W2H 55296
#define SM_W2L 64512
#define SM_RAW 73728      // 4 warp slabs x 5888B
#define SM_WROW (SM_RAW + 23552)
#define SMEM_MLP (SM_WROW + 512)

// one layer: 3-term fp16 split (ah*bh + al*bh + ah*bl); warp-local m=32
template<int KC>
__device__ __forceinline__ void do_layer(
    char* sm, uint32_t sb, uint32_t aH, uint32_t aL, uint32_t bH, uint32_t bL,
    const float* iv, float acc[2][8][4],
    int wid, int a_ro, int a_co, int b_ro, int b_co)
{
#pragma unroll
    for (int mi = 0; mi < 2; mi++)
#pragma unroll
        for (int ni = 0; ni < 8; ni++) {
            acc[mi][ni][0] = iv[2 * ni];
            acc[mi][ni][1] = iv[2 * ni + 1];
            acc[mi][ni][2] = iv[2 * ni];
            acc[mi][ni][3] = iv[2 * ni + 1];
        }
#pragma unroll
    for (int kc = 0; kc < KC; kc++) {
        uint32_t ah[2][4], al[2][4], bh[4][4], bl[4][4];
#pragma unroll
        for (int mi = 0; mi < 2; mi++) {
            uint32_t off = roff(wid * 32 + mi * 16 + a_ro, 2 * kc + a_co);
            ldsm4(ah[mi], sb + aH + off);
            ldsm4(al[mi], sb + aL + off);
        }
#pragma unroll
        for (int np = 0; np < 4; np++) {
            uint32_t off = roff(np * 16 + b_ro, 2 * kc + b_co);
            ldsm4(bh[np], sb + bH + off);
            ldsm4(bl[np], sb + bL + off);
        }
#pragma unroll
        for (int mi = 0; mi < 2; mi++)
#pragma unroll
            for (int ni = 0; ni < 8; ni++)
                mma16816(acc[mi][ni], ah[mi], &bh[ni >> 1][(ni & 1) * 2]);
#pragma unroll
        for (int mi = 0; mi < 2; mi++)
#pragma unroll
            for (int ni = 0; ni < 8; ni++)
                mma16816(acc[mi][ni], al[mi], &bh[ni >> 1][(ni & 1) * 2]);
#pragma unroll
        for (int mi = 0; mi < 2; mi++)
#pragma unroll
            for (int ni = 0; ni < 8; ni++)
                mma16816(acc[mi][ni], ah[mi], &bl[ni >> 1][(ni & 1) * 2]);
    }
}

__global__ void __launch_bounds__(128, 2)
k_mlp(const float* __restrict__ indiv, const unsigned char* __restrict__ mask_raw,
      const float* __restrict__ rets, const float* __restrict__ W1,
      const float* __restrict__ W2, const float* __restrict__ b2,
      const float* __restrict__ W3, const float* __restrict__ b3,
      float* __restrict__ out_w)
{
    extern __shared__ char sm[];
    const uint32_t sb = smem_u32(sm);
    float* wrow = (float*)(sm + SM_WROW);

    const int tid = threadIdx.x;
    const int wid = tid >> 5, lane = tid & 31;
    const int lq = lane & 7, qq = lane >> 3;
    const int a_ro = lq + ((qq & 1) << 3), a_co = qq >> 1;
    const int b_ro = lq + ((qq >> 1) << 3), b_co = qq & 1;
    const int cpair = (lane & 3) * 2;

    // ---- one-time weight staging (fp16 hi/lo, zero-pad K) ----
    for (int idx = tid; idx < 64 * 64; idx += 128) {
        int n = idx >> 6, k = idx & 63;
        float v1 = (k < DI) ? W1[n * FF + k] : 0.f;
        float v2 = W2[idx];
        uint32_t o = roff(n, k >> 3) + (k & 7) * 2;
        __half h, l;
        split_hf(v1, h, l);
        *(__half*)(sm + SM_W1H + o) = h;
        *(__half*)(sm + SM_W1L + o) = l;
        split_hf(v2, h, l);
        *(__half*)(sm + SM_W2H + o) = h;
        *(__half*)(sm + SM_W2L + o) = l;
    }
    float b2v[16], w3v[16];
#pragma unroll
    for (int ni = 0; ni < 8; ni++) {
        b2v[2 * ni]     = b2[ni * 8 + cpair];
        b2v[2 * ni + 1] = b2[ni * 8 + cpair + 1];
        w3v[2 * ni]     = W3[ni * 8 + cpair];
        w3v[2 * ni + 1] = W3[ni * 8 + cpair + 1];
    }
    const float b3v = b3[0];
    const int mask_kind = g_mask_kind;
    __syncthreads();

    float acc[2][8][4];
    const uint32_t slab = sb + SM_RAW + wid * 5888;
    const float* rawf = (const float*)(sm + SM_RAW + wid * 5888);

    auto stage = [&](int tile) {
        const int t = tile >> 5;
        const int p0 = (tile & 31) * TILE;
        if ((p0 + wid * 32) < NN) {
            const float4* gsrc = (const float4*)(indiv + ((size_t)t * NN + p0 + wid * 32) * DI);
#pragma unroll
            for (int i = lane; i < 368; i += 32)
                cp16(slab + (uint32_t)i * 16, gsrc + i);
            asm volatile("cp.async.commit_group;" ::: "memory");
        }
    };

    // prologue: stage first tile
    if (blockIdx.x < NTILES) stage(blockIdx.x);

    for (int tile = blockIdx.x; tile < NTILES; tile += gridDim.x) {
        const int t = tile >> 5;
        const int p0 = (tile & 31) * TILE;
        const int pg = p0 + tid;
        const bool valid = pg < NN;

        float m1v[16];
#pragma unroll
        for (int ni = 0; ni < 8; ni++) {
            m1v[2 * ni]     = __ldg(&g_macro1[t * 64 + ni * 8 + cpair]);
            m1v[2 * ni + 1] = __ldg(&g_macro1[t * 64 + ni * 8 + cpair + 1]);
        }
        asm volatile("cp.async.wait_group 0;" ::: "memory");
        __syncwarp();

        // ---- split own row to fp16 hi/lo, swizzled STS ----
        {
            const float* rp = rawf + lane * DI;
            const uint32_t rbase = (uint32_t)(tid * 144);
            const int rot0 = tid >> 3;
#pragma unroll
            for (int c = 0; c < 6; c++) {
                uint32_t hw[4], lw[4];
#pragma unroll
                for (int jp = 0; jp < 4; jp++) {
                    int c0 = c * 8 + 2 * jp, c1 = c0 + 1;
                    float x0 = (c0 < DI) ? rp[c0] : 0.f;
                    float x1 = (c1 < DI) ? rp[c1] : 0.f;
                    __half h0, l0, h1, l1;
                    split_hf(x0, h0, l0);
                    split_hf(x1, h1, l1);
                    hw[jp] = pkhf(h0, h1);
                    lw[jp] = pkhf(l0, l1);
                }
                uint32_t off = rbase + (uint32_t)(((c + rot0) % 9) * 16);
                *(uint4*)(sm + SM_XHI + off) = make_uint4(hw[0], hw[1], hw[2], hw[3]);
                *(uint4*)(sm + SM_XLO + off) = make_uint4(lw[0], lw[1], lw[2], lw[3]);
            }
        }
        __syncwarp();

        // layer 1: K=48
        do_layer<3>(sm, sb, SM_XHI, SM_XLO, SM_W1H, SM_W1L, m1v, acc,
                    wid, a_ro, a_co, b_ro, b_co);
        __syncwarp();

        // ---- prefetch NEXT tile's X into the (now dead) RAW slab ----
        // RAW was last read in the convert phase, >1500 cycles ago (ldsm/mma since).
        {
            int nxt = tile + gridDim.x;
            if (nxt < NTILES) stage(nxt);
        }

        // epilogue 1: relu + split, write A1 back (own rows)
#pragma unroll
        for (int mi = 0; mi < 2; mi++) {
            int R0 = wid * 32 + mi * 16 + (lane >> 2);
            int R1 = R0 + 8;
#pragma unroll
            for (int ni = 0; ni < 8; ni++) {
                float a0 = fmaxf(acc[mi][ni][0], 0.f);
                float a1 = fmaxf(acc[mi][ni][1], 0.f);
                float a2 = fmaxf(acc[mi][ni][2], 0.f);
                float a3 = fmaxf(acc[mi][ni][3], 0.f);
                __half h0, l0, h1, l1, h2, l2, h3, l3;
                split_hf(a0, h0, l0); split_hf(a1, h1, l1);
                split_hf(a2, h2, l2); split_hf(a3, h3, l3);
                uint32_t off0 = roff(R0, ni) + (lane & 3) * 4;
                uint32_t off1 = roff(R1, ni) + (lane & 3) * 4;
                *(uint32_t*)(sm + SM_XHI + off0) = pkhf(h0, h1);
                *(uint32_t*)(sm + SM_XLO + off0) = pkhf(l0, l1);
                *(uint32_t*)(sm + SM_XHI + off1) = pkhf(h2, h3);
                *(uint32_t*)(sm + SM_XLO + off1) = pkhf(l2, l3);
            }
        }
        __syncwarp();

        // layer 2: K=64
        do_layer<4>(sm, sb, SM_XHI, SM_XLO, SM_W2H, SM_W2L, b2v, acc,
                    wid, a_ro, a_co, b_ro, b_co);

        // epilogue 2: w3 dot relu -> per-row weight
        float ws[4] = {0.f, 0.f, 0.f, 0.f};
#pragma unroll
        for (int mi = 0; mi < 2; mi++)
#pragma unroll
            for (int ni = 0; ni < 8; ni++) {
                ws[2 * mi]     = fmaf(w3v[2 * ni], fmaxf(acc[mi][ni][0], 0.f),
                                 fmaf(w3v[2 * ni + 1], fmaxf(acc[mi][ni][1], 0.f), ws[2 * mi]));
                ws[2 * mi + 1] = fmaf(w3v[2 * ni], fmaxf(acc[mi][ni][2], 0.f),
                                 fmaf(w3v[2 * ni + 1], fmaxf(acc[mi][ni][3], 0.f), ws[2 * mi + 1]));
            }
#pragma unroll
        for (int i = 0; i < 4; i++) {
            ws[i] += __shfl_xor_sync(0xffffffffu, ws[i], 1);
            ws[i] += __shfl_xor_sync(0xffffffffu, ws[i], 2);
        }
        float* wrowW = wrow + wid * 32;
        if ((lane & 3) == 0) {
            int r = lane >> 2;
            wrowW[r] = ws[0]; wrowW[r + 8] = ws[1];
            wrowW[r + 16] = ws[2]; wrowW[r + 24] = ws[3];
        }
        __syncwarp();

        // per-point finish
        float contrib = 0.f, mval = 0.f;
        {
            float w = wrowW[lane] + b3v;
            if (valid) {
                size_t gi = (size_t)t * NN + pg;
                float mf = (mask_kind == 0) ? (float)mask_raw[gi]
                         : (mask_kind == 1) ? (float)((const int*)mask_raw)[gi]
                         : ((const float*)mask_raw)[gi];
                float wm = w * mf;
                out_w[gi] = wm;
                contrib = wm * rets[gi];
                mval = mf;
            }
        }
#pragma unroll
        for (int off = 16; off; off >>= 1) {
            contrib += __shfl_down_sync(0xffffffffu, contrib, off);
            mval    += __shfl_down_sync(0xffffffffu, mval, off);
        }
        if (lane == 0) {
            atomicAdd(&g_sum[t], contrib);
            atomicAdd(&g_cnt[t], mval);
        }
    }
}

// ---------- K5: sdf finalize ----------
__global__ void __launch_bounds__(256) k_final(float* __restrict__ out_sdf) {
    __shared__ float smr[256];
    int t = threadIdx.x;
    float cnt = g_cnt[t];
    smr[t] = cnt;
    __syncthreads();
    for (int s = 128; s > 0; s >>= 1) {
        if (t < s) smr[t] += smr[t + s];
        __syncthreads();
    }
    float mean = smr[0] * (1.0f / 256.0f);
    out_sdf[t] = g_sum[t] / cnt * mean + 1.0f;
}

// ---------- launch ----------
extern "C" void kernel_launch(void* const* d_in, const int* in_sizes, int n_in,
                              void* d_out, int out_size) {
    (void)in_sizes; (void)n_in; (void)out_size;
    const float* macro = (const float*)d_in[0];
    const float* indiv = (const float*)d_in[1];
    const unsigned char* masks = (const unsigned char*)d_in[2];
    const float* rets  = (const float*)d_in[3];
    const float* W_ih  = (const float*)d_in[4];
    const float* W_hh  = (const float*)d_in[5];
    const float* b_ih  = (const float*)d_in[6];
    const float* b_hh  = (const float*)d_in[7];
    const float* W1    = (const float*)d_in[8];
    const float* b1    = (const float*)d_in[9];
    const float* W2    = (const float*)d_in[10];
    const float* b2    = (const float*)d_in[11];
    const float* W3    = (const float*)d_in[12];
    const float* b3    = (const float*)d_in[13];

    float* out     = (float*)d_out;
    float* out_sdf = out;          // sdf [T,1]
    float* out_w   = out + T_;     // weights [1,T,N,1]

    cudaFuncSetAttribute(k_mlp, cudaFuncAttributeMaxDynamicSharedMemorySize, SMEM_MLP);

    k_prep<<<T_, 256>>>(macro, W_ih, b_ih, b_hh, masks);
    k_lstm<<<1, G4>>>(W_hh);
    k_macro1<<<T_ / 4, 256>>>(W1, b1);
    k_mlp<<<GRID_MLP, 128, SMEM_MLP>>>(indiv, masks, rets, W1, W2, b2, W3, b3, out_w);
    k_final<<<1, T_>>>(out_sdf);
}

// round 10
// speedup vs baseline: 2.7751x; 1.0376x over previous
#include <cuda_runtime.h>
#include <cuda_fp16.h>
#include <cstdint>

#define T_  256
#define NN  4000
#define DM  178
#define DI  46
#define H_  64
#define DH  64
#define FF  110   // DI + H
#define G4  256   // 4*H
#define TILE 128
#define NTILES (T_ * 32)   // 8192
#define GRID_MLP 296

typedef unsigned long long u64;

// ---------- device scratch ----------
__device__ float g_XZ[T_ * G4];
__device__ float g_macro1[T_ * DH];
__device__ float g_sum[T_];
__device__ float g_cnt[T_];
__device__ int   g_mask_kind;   // 0=uint8/bool, 1=int32, 2=float32

// ---------- packed f32x2 helpers ----------
__device__ __forceinline__ u64 pk2(float lo, float hi) {
    u64 r; asm("mov.b64 %0, {%1, %2};" : "=l"(r) : "f"(lo), "f"(hi)); return r;
}
__device__ __forceinline__ u64 ffma2(u64 a, u64 b, u64 c) {
    u64 d; asm("fma.rn.f32x2 %0, %1, %2, %3;" : "=l"(d) : "l"(a), "l"(b), "l"(c)); return d;
}
__device__ __forceinline__ float2 up2(u64 a) {
    float2 f; asm("mov.b64 {%0, %1}, %2;" : "=f"(f.x), "=f"(f.y) : "l"(a)); return f;
}

// ---------- activations ----------
__device__ __forceinline__ float sigm(float x) {
    float e = exp2f(-1.44269504088896340736f * x);
    return __fdividef(1.0f, 1.0f + e);
}
__device__ __forceinline__ float tanh_(float x) {
    float a = fabsf(x);
    float e = exp2f(-2.88539008177792681472f * a);
    float r = __fdividef(1.0f - e, 1.0f + e);
    return copysignf(r, x);
}

// ---------- warp MMA helpers ----------
__device__ __forceinline__ uint32_t smem_u32(const void* p) {
    uint32_t a;
    asm("{ .reg .u64 t; cvta.to.shared.u64 t, %1; cvt.u32.u64 %0, t; }" : "=r"(a) : "l"(p));
    return a;
}
__device__ __forceinline__ void ldsm4(uint32_t* r, uint32_t addr) {
    asm volatile("ldmatrix.sync.aligned.m8n8.x4.shared.b16 {%0,%1,%2,%3}, [%4];"
        : "=r"(r[0]), "=r"(r[1]), "=r"(r[2]), "=r"(r[3]) : "r"(addr));
}
__device__ __forceinline__ void mma16816(float* d, const uint32_t* a, const uint32_t* b) {
    asm volatile("mma.sync.aligned.m16n8k16.row.col.f32.f16.f16.f32 "
        "{%0,%1,%2,%3}, {%4,%5,%6,%7}, {%8,%9}, {%0,%1,%2,%3};"
        : "+f"(d[0]), "+f"(d[1]), "+f"(d[2]), "+f"(d[3])
        : "r"(a[0]), "r"(a[1]), "r"(a[2]), "r"(a[3]), "r"(b[0]), "r"(b[1]));
}
__device__ __forceinline__ uint32_t pkhf(__half a, __half b) {
    return ((uint32_t)__half_as_ushort(b) << 16) | (uint32_t)__half_as_ushort(a);
}
__device__ __forceinline__ void split_hf(float x, __half& h, __half& l) {
    h = __float2half_rn(x);
    l = __float2half_rn(x - __half2float(h));
}
// row/chunk -> byte offset: 144B row stride, chunk rotation mod 9
__device__ __forceinline__ uint32_t roff(int r, int c) {
    return (uint32_t)(r * 144 + ((c + (r >> 3)) % 9) * 16);
}
__device__ __forceinline__ void cp16(uint32_t saddr, const void* gaddr) {
    asm volatile("cp.async.cg.shared.global [%0], [%1], 16;" :: "r"(saddr), "l"(gaddr));
}

// ---------- K1: XZ with smem-cached W slice (64 blocks) + mask detect ----------
// grid: 64 blocks = (gg 0..3 gate-group) x (tg 0..15 t-group); 256 threads.
#define PREP_SMEM ((64 * 185 + 16 * DM) * 4)
__global__ void __launch_bounds__(256) k_prep(const float* __restrict__ macro,
                                              const float* __restrict__ W_ih,
                                              const float* __restrict__ b_ih,
                                              const float* __restrict__ b_hh,
                                              const unsigned char* __restrict__ masks) {
    extern __shared__ float psm[];
    float* Wsm = psm;                 // [64][185]
    float* xs  = psm + 64 * 185;      // [16][178]
    const int tid = threadIdx.x;
    const int gg = blockIdx.x & 3, tg = blockIdx.x >> 2;

    for (int idx = tid; idx < 64 * DM; idx += 256) {
        int g = idx / DM, k = idx - g * DM;
        Wsm[g * 185 + k] = W_ih[(size_t)(gg * 64 + g) * DM + k];
    }
    for (int idx = tid; idx < 16 * DM; idx += 256) {
        int tt = idx / DM, k = idx - tt * DM;
        xs[tt * DM + k] = macro[(size_t)(tg * 16 + tt) * DM + k];
    }
    if (gg == 0 && tid < 16) {
        g_sum[tg * 16 + tid] = 0.f;
        g_cnt[tg * 16 + tid] = 0.f;
    }
    __syncthreads();

    const int g = tid & 63, tq = tid >> 6;
    const float bsum = b_ih[gg * 64 + g] + b_hh[gg * 64 + g];
    const float* wrow = Wsm + g * 185;
    for (int tt = tq; tt < 16; tt += 4) {
        const float* xr = xs + tt * DM;
        float a0 = 0.f, a1 = 0.f, a2 = 0.f, a3 = 0.f;
#pragma unroll 4
        for (int k = 0; k < 176; k += 4) {
            a0 = fmaf(wrow[k],     xr[k],     a0);
            a1 = fmaf(wrow[k + 1], xr[k + 1], a1);
            a2 = fmaf(wrow[k + 2], xr[k + 2], a2);
            a3 = fmaf(wrow[k + 3], xr[k + 3], a3);
        }
        a0 = fmaf(wrow[176], xr[176], a0);
        a1 = fmaf(wrow[177], xr[177], a1);
        g_XZ[(tg * 16 + tt) * G4 + gg * 64 + g] = ((a0 + a1) + (a2 + a3)) + bsum;
    }

    if (blockIdx.x == 0) {
        __shared__ int s_any, s_flt;
        if (tid == 0) { s_any = 0; s_flt = 0; }
        __syncthreads();
        int ta = 0, tf = 0;
        for (int j = tid; j < 1024; j += 256) {
            unsigned char c1 = masks[4 * j + 1], c2 = masks[4 * j + 2], c3 = masks[4 * j + 3];
            if (c1 | c2 | c3) ta = 1;
            if (c3 == 0x3F) tf = 1;
        }
        if (ta) atomicOr(&s_any, 1);
        if (tf) atomicOr(&s_flt, 1);
        __syncthreads();
        if (tid == 0) g_mask_kind = s_flt ? 2 : (s_any ? 0 : 1);
    }
}

// ---------- K2: LSTM scan (shfl gate exchange, 1 sync/step) + fused macro1 ----------
// thread: unit j = tid>>2, role rr = tid&3 (0=i,1=f,2=g,3=o); gate row = rr*64+j.
// h history kept in smem: hs[(T_+1)][64]; hs[0] = 0.
#define LSTM_SMEM ((T_ + 1) * H_ * 4)
__global__ void __launch_bounds__(256, 1) k_lstm(const float* __restrict__ W_hh,
                                                 const float* __restrict__ W1,
                                                 const float* __restrict__ b1) {
    extern __shared__ float hs[];
    const int tid = threadIdx.x;
    const int lane = tid & 31;
    const int j = tid >> 2, rr = tid & 3;
    const int row = rr * 64 + j;

    // gate weights in registers (packed pairs)
    u64 w[32];
    {
        const float4* wr = (const float4*)(W_hh + (size_t)row * H_);
#pragma unroll
        for (int k = 0; k < 16; k++) {
            float4 v = wr[k];
            w[2 * k] = pk2(v.x, v.y);
            w[2 * k + 1] = pk2(v.z, v.w);
        }
    }
    if (tid < H_) hs[tid] = 0.f;   // h_{-1}
    float c = 0.f;
    float zc = g_XZ[row];
    __syncthreads();

    const u64 one = pk2(1.f, 1.f);
    const int base = lane & ~3;
    for (int t = 0; t < T_; t++) {
        const u64* h64 = (const u64*)(hs + t * H_);   // h_{t-1}
        u64 a0 = pk2(0.f, 0.f), a1 = a0, a2 = a0, a3 = a0;
#pragma unroll
        for (int k = 0; k < 32; k += 4) {
            a0 = ffma2(w[k],     h64[k],     a0);
            a1 = ffma2(w[k + 1], h64[k + 1], a1);
            a2 = ffma2(w[k + 2], h64[k + 2], a2);
            a3 = ffma2(w[k + 3], h64[k + 3], a3);
        }
        a0 = ffma2(one, a1, a0);
        a2 = ffma2(one, a3, a2);
        float2 s0 = up2(a0), s2 = up2(a2);
        float z = zc + ((s0.x + s0.y) + (s2.x + s2.y));
        if (t + 1 < T_) zc = g_XZ[(t + 1) * G4 + row];

        float a = (rr == 2) ? tanh_(z) : sigm(z);
        float af = __shfl_sync(0xffffffffu, a, base + 1);
        float ag = __shfl_sync(0xffffffffu, a, base + 2);
        float ao = __shfl_sync(0xffffffffu, a, base + 3);
        if (rr == 0) {
            c = fmaf(af, c, a * ag);          // c = f*c + i*g
            hs[(t + 1) * H_ + j] = ao * tanh_(c);
        }
        __syncthreads();
    }

    // ---- fused macro1: m1[t][o] = b1[o] + W1[o][DI:] @ h_t ----
    const int o = tid & 63, tq = tid >> 6;
    u64 wm[32];
    {
        const float2* wr = (const float2*)(W1 + (size_t)o * FF + DI);   // 8B aligned
#pragma unroll
        for (int k = 0; k < 32; k++) { float2 v = wr[k]; wm[k] = pk2(v.x, v.y); }
    }
    const float b1v = b1[o];
    for (int t = tq; t < T_; t += 4) {
        const u64* h64 = (const u64*)(hs + (t + 1) * H_);
        u64 a0 = pk2(0.f, 0.f), a1 = a0, a2 = a0, a3 = a0;
#pragma unroll
        for (int k = 0; k < 32; k += 4) {
            a0 = ffma2(wm[k],     h64[k],     a0);
            a1 = ffma2(wm[k + 1], h64[k + 1], a1);
            a2 = ffma2(wm[k + 2], h64[k + 2], a2);
            a3 = ffma2(wm[k + 3], h64[k + 3], a3);
        }
        a0 = ffma2(one, a1, a0);
        a2 = ffma2(one, a3, a2);
        float2 s0 = up2(a0), s2 = up2(a2);
        g_macro1[t * DH + o] = ((s0.x + s0.y) + (s2.x + s2.y)) + b1v;
    }
}

// ---------- K4: warp-MMA fused MLP (R9, measured 159us) ----------
#define SM_XHI 0
#define SM_XLO 18432
#define SM_W1H 36864
#define SM_W1L 46080
#define SM_W2H 55296
#define SM_W2L 64512
#define SM_RAW 73728      // 4 warp slabs x 5888B
#define SM_WROW (SM_RAW + 23552)
#define SMEM_MLP (SM_WROW + 512)

template<int KC>
__device__ __forceinline__ void do_layer(
    char* sm, uint32_t sb, uint32_t aH, uint32_t aL, uint32_t bH, uint32_t bL,
    const float* iv, float acc[2][8][4],
    int wid, int a_ro, int a_co, int b_ro, int b_co)
{
#pragma unroll
    for (int mi = 0; mi < 2; mi++)
#pragma unroll
        for (int ni = 0; ni < 8; ni++) {
            acc[mi][ni][0] = iv[2 * ni];
            acc[mi][ni][1] = iv[2 * ni + 1];
            acc[mi][ni][2] = iv[2 * ni];
            acc[mi][ni][3] = iv[2 * ni + 1];
        }
#pragma unroll
    for (int kc = 0; kc < KC; kc++) {
        uint32_t ah[2][4], al[2][4], bh[4][4], bl[4][4];
#pragma unroll
        for (int mi = 0; mi < 2; mi++) {
            uint32_t off = roff(wid * 32 + mi * 16 + a_ro, 2 * kc + a_co);
            ldsm4(ah[mi], sb + aH + off);
            ldsm4(al[mi], sb + aL + off);
        }
#pragma unroll
        for (int np = 0; np < 4; np++) {
            uint32_t off = roff(np * 16 + b_ro, 2 * kc + b_co);
            ldsm4(bh[np], sb + bH + off);
            ldsm4(bl[np], sb + bL + off);
        }
#pragma unroll
        for (int mi = 0; mi < 2; mi++)
#pragma unroll
            for (int ni = 0; ni < 8; ni++)
                mma16816(acc[mi][ni], ah[mi], &bh[ni >> 1][(ni & 1) * 2]);
#pragma unroll
        for (int mi = 0; mi < 2; mi++)
#pragma unroll
            for (int ni = 0; ni < 8; ni++)
                mma16816(acc[mi][ni], al[mi], &bh[ni >> 1][(ni & 1) * 2]);
#pragma unroll
        for (int mi = 0; mi < 2; mi++)
#pragma unroll
            for (int ni = 0; ni < 8; ni++)
                mma16816(acc[mi][ni], ah[mi], &bl[ni >> 1][(ni & 1) * 2]);
    }
}

__global__ void __launch_bounds__(128, 2)
k_mlp(const float* __restrict__ indiv, const unsigned char* __restrict__ mask_raw,
      const float* __restrict__ rets, const float* __restrict__ W1,
      const float* __restrict__ W2, const float* __restrict__ b2,
      const float* __restrict__ W3, const float* __restrict__ b3,
      float* __restrict__ out_w)
{
    extern __shared__ char sm[];
    const uint32_t sb = smem_u32(sm);
    float* wrow = (float*)(sm + SM_WROW);

    const int tid = threadIdx.x;
    const int wid = tid >> 5, lane = tid & 31;
    const int lq = lane & 7, qq = lane >> 3;
    const int a_ro = lq + ((qq & 1) << 3), a_co = qq >> 1;
    const int b_ro = lq + ((qq >> 1) << 3), b_co = qq & 1;
    const int cpair = (lane & 3) * 2;

    for (int idx = tid; idx < 64 * 64; idx += 128) {
        int n = idx >> 6, k = idx & 63;
        float v1 = (k < DI) ? W1[n * FF + k] : 0.f;
        float v2 = W2[idx];
        uint32_t o = roff(n, k >> 3) + (k & 7) * 2;
        __half h, l;
        split_hf(v1, h, l);
        *(__half*)(sm + SM_W1H + o) = h;
        *(__half*)(sm + SM_W1L + o) = l;
        split_hf(v2, h, l);
        *(__half*)(sm + SM_W2H + o) = h;
        *(__half*)(sm + SM_W2L + o) = l;
    }
    float b2v[16], w3v[16];
#pragma unroll
    for (int ni = 0; ni < 8; ni++) {
        b2v[2 * ni]     = b2[ni * 8 + cpair];
        b2v[2 * ni + 1] = b2[ni * 8 + cpair + 1];
        w3v[2 * ni]     = W3[ni * 8 + cpair];
        w3v[2 * ni + 1] = W3[ni * 8 + cpair + 1];
    }
    const float b3v = b3[0];
    const int mask_kind = g_mask_kind;
    __syncthreads();

    float acc[2][8][4];
    const uint32_t slab = sb + SM_RAW + wid * 5888;
    const float* rawf = (const float*)(sm + SM_RAW + wid * 5888);

    auto stage = [&](int tile) {
        const int t = tile >> 5;
        const int p0 = (tile & 31) * TILE;
        if ((p0 + wid * 32) < NN) {
            const float4* gsrc = (const float4*)(indiv + ((size_t)t * NN + p0 + wid * 32) * DI);
#pragma unroll
            for (int i = lane; i < 368; i += 32)
                cp16(slab + (uint32_t)i * 16, gsrc + i);
            asm volatile("cp.async.commit_group;" ::: "memory");
        }
    };

    if (blockIdx.x < NTILES) stage(blockIdx.x);

    for (int tile = blockIdx.x; tile < NTILES; tile += gridDim.x) {
        const int t = tile >> 5;
        const int p0 = (tile & 31) * TILE;
        const int pg = p0 + tid;
        const bool valid = pg < NN;

        float m1v[16];
#pragma unroll
        for (int ni = 0; ni < 8; ni++) {
            m1v[2 * ni]     = __ldg(&g_macro1[t * 64 + ni * 8 + cpair]);
            m1v[2 * ni + 1] = __ldg(&g_macro1[t * 64 + ni * 8 + cpair + 1]);
        }
        asm volatile("cp.async.wait_group 0;" ::: "memory");
        __syncwarp();

        {
            const float* rp = rawf + lane * DI;
            const uint32_t rbase = (uint32_t)(tid * 144);
            const int rot0 = tid >> 3;
#pragma unroll
            for (int c = 0; c < 6; c++) {
                uint32_t hw[4], lw[4];
#pragma unroll
                for (int jp = 0; jp < 4; jp++) {
                    int c0 = c * 8 + 2 * jp, c1 = c0 + 1;
                    float x0 = (c0 < DI) ? rp[c0] : 0.f;
                    float x1 = (c1 < DI) ? rp[c1] : 0.f;
                    __half h0, l0, h1, l1;
                    split_hf(x0, h0, l0);
                    split_hf(x1, h1, l1);
                    hw[jp] = pkhf(h0, h1);
                    lw[jp] = pkhf(l0, l1);
                }
                uint32_t off = rbase + (uint32_t)(((c + rot0) % 9) * 16);
                *(uint4*)(sm + SM_XHI + off) = make_uint4(hw[0], hw[1], hw[2], hw[3]);
                *(uint4*)(sm + SM_XLO + off) = make_uint4(lw[0], lw[1], lw[2], lw[3]);
            }
        }
        __syncwarp();

        do_layer<3>(sm, sb, SM_XHI, SM_XLO, SM_W1H, SM_W1L, m1v, acc,
                    wid, a_ro, a_co, b_ro, b_co);
        __syncwarp();

        {
            int nxt = tile + gridDim.x;
            if (nxt < NTILES) stage(nxt);
        }

#pragma unroll
        for (int mi = 0; mi < 2; mi++) {
            int R0 = wid * 32 + mi * 16 + (lane >> 2);
            int R1 = R0 + 8;
#pragma unroll
            for (int ni = 0; ni < 8; ni++) {
                float a0 = fmaxf(acc[mi][ni][0], 0.f);
                float a1 = fmaxf(acc[mi][ni][1], 0.f);
                float a2 = fmaxf(acc[mi][ni][2], 0.f);
                float a3 = fmaxf(acc[mi][ni][3], 0.f);
                __half h0, l0, h1, l1, h2, l2, h3, l3;
                split_hf(a0, h0, l0); split_hf(a1, h1, l1);
                split_hf(a2, h2, l2); split_hf(a3, h3, l3);
                uint32_t off0 = roff(R0, ni) + (lane & 3) * 4;
                uint32_t off1 = roff(R1, ni) + (lane & 3) * 4;
                *(uint32_t*)(sm + SM_XHI + off0) = pkhf(h0, h1);
                *(uint32_t*)(sm + SM_XLO + off0) = pkhf(l0, l1);
                *(uint32_t*)(sm + SM_XHI + off1) = pkhf(h2, h3);
                *(uint32_t*)(sm + SM_XLO + off1) = pkhf(l2, l3);
            }
        }
        __syncwarp();

        do_layer<4>(sm, sb, SM_XHI, SM_XLO, SM_W2H, SM_W2L, b2v, acc,
                    wid, a_ro, a_co, b_ro, b_co);

        float ws[4] = {0.f, 0.f, 0.f, 0.f};
#pragma unroll
        for (int mi = 0; mi < 2; mi++)
#pragma unroll
            for (int ni = 0; ni < 8; ni++) {
                ws[2 * mi]     = fmaf(w3v[2 * ni], fmaxf(acc[mi][ni][0], 0.f),
                                 fmaf(w3v[2 * ni + 1], fmaxf(acc[mi][ni][1], 0.f), ws[2 * mi]));
                ws[2 * mi + 1] = fmaf(w3v[2 * ni], fmaxf(acc[mi][ni][2], 0.f),
                                 fmaf(w3v[2 * ni + 1], fmaxf(acc[mi][ni][3], 0.f), ws[2 * mi + 1]));
            }
#pragma unroll
        for (int i = 0; i < 4; i++) {
            ws[i] += __shfl_xor_sync(0xffffffffu, ws[i], 1);
            ws[i] += __shfl_xor_sync(0xffffffffu, ws[i], 2);
        }
        float* wrowW = wrow + wid * 32;
        if ((lane & 3) == 0) {
            int r = lane >> 2;
            wrowW[r] = ws[0]; wrowW[r + 8] = ws[1];
            wrowW[r + 16] = ws[2]; wrowW[r + 24] = ws[3];
        }
        __syncwarp();

        float contrib = 0.f, mval = 0.f;
        {
            float w = wrowW[lane] + b3v;
            if (valid) {
                size_t gi = (size_t)t * NN + pg;
                float mf = (mask_kind == 0) ? (float)mask_raw[gi]
                         : (mask_kind == 1) ? (float)((const int*)mask_raw)[gi]
                         : ((const float*)mask_raw)[gi];
                float wm = w * mf;
                out_w[gi] = wm;
                contrib = wm * rets[gi];
                mval = mf;
            }
        }
#pragma unroll
        for (int off = 16; off; off >>= 1) {
            contrib += __shfl_down_sync(0xffffffffu, contrib, off);
            mval    += __shfl_down_sync(0xffffffffu, mval, off);
        }
        if (lane == 0) {
            atomicAdd(&g_sum[t], contrib);
            atomicAdd(&g_cnt[t], mval);
        }
    }
}

// ---------- K5: sdf finalize ----------
__global__ void __launch_bounds__(256) k_final(float* __restrict__ out_sdf) {
    __shared__ float smr[256];
    int t = threadIdx.x;
    float cnt = g_cnt[t];
    smr[t] = cnt;
    __syncthreads();
    for (int s = 128; s > 0; s >>= 1) {
        if (t < s) smr[t] += smr[t + s];
        __syncthreads();
    }
    float mean = smr[0] * (1.0f / 256.0f);
    out_sdf[t] = g_sum[t] / cnt * mean + 1.0f;
}

// ---------- launch ----------
extern "C" void kernel_launch(void* const* d_in, const int* in_sizes, int n_in,
                              void* d_out, int out_size) {
    (void)in_sizes; (void)n_in; (void)out_size;
    const float* macro = (const float*)d_in[0];
    const float* indiv = (const float*)d_in[1];
    const unsigned char* masks = (const unsigned char*)d_in[2];
    const float* rets  = (const float*)d_in[3];
    const float* W_ih  = (const float*)d_in[4];
    const float* W_hh  = (const float*)d_in[5];
    const float* b_ih  = (const float*)d_in[6];
    const float* b_hh  = (const float*)d_in[7];
    const float* W1    = (const float*)d_in[8];
    const float* b1    = (const float*)d_in[9];
    const float* W2    = (const float*)d_in[10];
    const float* b2    = (const float*)d_in[11];
    const float* W3    = (const float*)d_in[12];
    const float* b3    = (const float*)d_in[13];

    float* out     = (float*)d_out;
    float* out_sdf = out;          // sdf [T,1]
    float* out_w   = out + T_;     // weights [1,T,N,1]

    cudaFuncSetAttribute(k_prep, cudaFuncAttributeMaxDynamicSharedMemorySize, PREP_SMEM);
    cudaFuncSetAttribute(k_lstm, cudaFuncAttributeMaxDynamicSharedMemorySize, LSTM_SMEM);
    cudaFuncSetAttribute(k_mlp,  cudaFuncAttributeMaxDynamicSharedMemorySize, SMEM_MLP);

    k_prep<<<64, 256, PREP_SMEM>>>(macro, W_ih, b_ih, b_hh, masks);
    k_lstm<<<1, 256, LSTM_SMEM>>>(W_hh, W1, b1);
    k_mlp<<<GRID_MLP, 128, SMEM_MLP>>>(indiv, masks, rets, W1, W2, b2, W3, b3, out_w);
    k_final<<<1, T_>>>(out_sdf);
}

// round 11
// speedup vs baseline: 2.9015x; 1.0455x over previous
#include <cuda_runtime.h>
#include <cuda_fp16.h>
#include <cstdint>

#define T_  256
#define NN  4000
#define DM  178
#define DI  46
#define H_  64
#define DH  64
#define FF  110   // DI + H
#define G4  256   // 4*H
#define TILE 128
#define NTILES (T_ * 32)   // 8192
#define GRID_MLP 296

typedef unsigned long long u64;

// ---------- device scratch ----------
__device__ float g_XZ[T_ * G4];
__device__ float g_macro1[T_ * DH];
__device__ float g_sum[T_];
__device__ float g_cnt[T_];
__device__ int   g_mask_kind;   // 0=uint8/bool, 1=int32, 2=float32

// ---------- packed f32x2 helpers ----------
__device__ __forceinline__ u64 pk2(float lo, float hi) {
    u64 r; asm("mov.b64 %0, {%1, %2};" : "=l"(r) : "f"(lo), "f"(hi)); return r;
}
__device__ __forceinline__ u64 ffma2(u64 a, u64 b, u64 c) {
    u64 d; asm("fma.rn.f32x2 %0, %1, %2, %3;" : "=l"(d) : "l"(a), "l"(b), "l"(c)); return d;
}
__device__ __forceinline__ float2 up2(u64 a) {
    float2 f; asm("mov.b64 {%0, %1}, %2;" : "=f"(f.x), "=f"(f.y) : "l"(a)); return f;
}

// ---------- activations ----------
__device__ __forceinline__ float sigm(float x) {
    float e = exp2f(-1.44269504088896340736f * x);
    return __fdividef(1.0f, 1.0f + e);
}
__device__ __forceinline__ float tanh_(float x) {
    float a = fabsf(x);
    float e = exp2f(-2.88539008177792681472f * a);
    float r = __fdividef(1.0f - e, 1.0f + e);
    return copysignf(r, x);
}

// ---------- warp MMA helpers ----------
__device__ __forceinline__ uint32_t smem_u32(const void* p) {
    uint32_t a;
    asm("{ .reg .u64 t; cvta.to.shared.u64 t, %1; cvt.u32.u64 %0, t; }" : "=r"(a) : "l"(p));
    return a;
}
__device__ __forceinline__ void ldsm4(uint32_t* r, uint32_t addr) {
    asm volatile("ldmatrix.sync.aligned.m8n8.x4.shared.b16 {%0,%1,%2,%3}, [%4];"
        : "=r"(r[0]), "=r"(r[1]), "=r"(r[2]), "=r"(r[3]) : "r"(addr));
}
__device__ __forceinline__ void mma16816(float* d, const uint32_t* a, const uint32_t* b) {
    asm volatile("mma.sync.aligned.m16n8k16.row.col.f32.f16.f16.f32 "
        "{%0,%1,%2,%3}, {%4,%5,%6,%7}, {%8,%9}, {%0,%1,%2,%3};"
        : "+f"(d[0]), "+f"(d[1]), "+f"(d[2]), "+f"(d[3])
        : "r"(a[0]), "r"(a[1]), "r"(a[2]), "r"(a[3]), "r"(b[0]), "r"(b[1]));
}
__device__ __forceinline__ uint32_t pkhf(__half a, __half b) {
    return ((uint32_t)__half_as_ushort(b) << 16) | (uint32_t)__half_as_ushort(a);
}
__device__ __forceinline__ void split_hf(float x, __half& h, __half& l) {
    h = __float2half_rn(x);
    l = __float2half_rn(x - __half2float(h));
}
// row/chunk -> byte offset: 144B row stride, chunk rotation mod 9
__device__ __forceinline__ uint32_t roff(int r, int c) {
    return (uint32_t)(r * 144 + ((c + (r >> 3)) % 9) * 16);
}
__device__ __forceinline__ void cp16(uint32_t saddr, const void* gaddr) {
    asm volatile("cp.async.cg.shared.global [%0], [%1], 16;" :: "r"(saddr), "l"(gaddr));
}

// ---------- K1: XZ with smem-cached W slice (64 blocks) + mask detect ----------
#define PREP_SMEM ((64 * 185 + 16 * DM) * 4)
__global__ void __launch_bounds__(256) k_prep(const float* __restrict__ macro,
                                              const float* __restrict__ W_ih,
                                              const float* __restrict__ b_ih,
                                              const float* __restrict__ b_hh,
                                              const unsigned char* __restrict__ masks) {
    extern __shared__ float psm[];
    float* Wsm = psm;                 // [64][185]
    float* xs  = psm + 64 * 185;      // [16][178]
    const int tid = threadIdx.x;
    const int gg = blockIdx.x & 3, tg = blockIdx.x >> 2;

    for (int idx = tid; idx < 64 * DM; idx += 256) {
        int g = idx / DM, k = idx - g * DM;
        Wsm[g * 185 + k] = W_ih[(size_t)(gg * 64 + g) * DM + k];
    }
    for (int idx = tid; idx < 16 * DM; idx += 256) {
        int tt = idx / DM, k = idx - tt * DM;
        xs[tt * DM + k] = macro[(size_t)(tg * 16 + tt) * DM + k];
    }
    if (gg == 0 && tid < 16) {
        g_sum[tg * 16 + tid] = 0.f;
        g_cnt[tg * 16 + tid] = 0.f;
    }
    __syncthreads();

    const int g = tid & 63, tq = tid >> 6;
    const float bsum = b_ih[gg * 64 + g] + b_hh[gg * 64 + g];
    const float* wrow = Wsm + g * 185;
    for (int tt = tq; tt < 16; tt += 4) {
        const float* xr = xs + tt * DM;
        float a0 = 0.f, a1 = 0.f, a2 = 0.f, a3 = 0.f;
#pragma unroll 4
        for (int k = 0; k < 176; k += 4) {
            a0 = fmaf(wrow[k],     xr[k],     a0);
            a1 = fmaf(wrow[k + 1], xr[k + 1], a1);
            a2 = fmaf(wrow[k + 2], xr[k + 2], a2);
            a3 = fmaf(wrow[k + 3], xr[k + 3], a3);
        }
        a0 = fmaf(wrow[176], xr[176], a0);
        a1 = fmaf(wrow[177], xr[177], a1);
        g_XZ[(tg * 16 + tt) * G4 + gg * 64 + g] = ((a0 + a1) + (a2 + a3)) + bsum;
    }

    if (blockIdx.x == 0) {
        __shared__ int s_any, s_flt;
        if (tid == 0) { s_any = 0; s_flt = 0; }
        __syncthreads();
        int ta = 0, tf = 0;
        for (int j = tid; j < 1024; j += 256) {
            unsigned char c1 = masks[4 * j + 1], c2 = masks[4 * j + 2], c3 = masks[4 * j + 3];
            if (c1 | c2 | c3) ta = 1;
            if (c3 == 0x3F) tf = 1;
        }
        if (ta) atomicOr(&s_any, 1);
        if (tf) atomicOr(&s_flt, 1);
        __syncthreads();
        if (tid == 0) g_mask_kind = s_flt ? 2 : (s_any ? 0 : 1);
    }
}

// ---------- K2: LSTM scan (shfl gate exchange, 1 sync/step) + fused macro1 ----------
#define LSTM_SMEM ((T_ + 1) * H_ * 4)
__global__ void __launch_bounds__(256, 1) k_lstm(const float* __restrict__ W_hh,
                                                 const float* __restrict__ W1,
                                                 const float* __restrict__ b1) {
    extern __shared__ float hs[];
    const int tid = threadIdx.x;
    const int lane = tid & 31;
    const int j = tid >> 2, rr = tid & 3;
    const int row = rr * 64 + j;

    u64 w[32];
    {
        const float4* wr = (const float4*)(W_hh + (size_t)row * H_);
#pragma unroll
        for (int k = 0; k < 16; k++) {
            float4 v = wr[k];
            w[2 * k] = pk2(v.x, v.y);
            w[2 * k + 1] = pk2(v.z, v.w);
        }
    }
    if (tid < H_) hs[tid] = 0.f;
    float c = 0.f;
    float zc = g_XZ[row];
    __syncthreads();

    const u64 one = pk2(1.f, 1.f);
    const int base = lane & ~3;
    for (int t = 0; t < T_; t++) {
        const u64* h64 = (const u64*)(hs + t * H_);
        u64 a0 = pk2(0.f, 0.f), a1 = a0, a2 = a0, a3 = a0;
#pragma unroll
        for (int k = 0; k < 32; k += 4) {
            a0 = ffma2(w[k],     h64[k],     a0);
            a1 = ffma2(w[k + 1], h64[k + 1], a1);
            a2 = ffma2(w[k + 2], h64[k + 2], a2);
            a3 = ffma2(w[k + 3], h64[k + 3], a3);
        }
        a0 = ffma2(one, a1, a0);
        a2 = ffma2(one, a3, a2);
        float2 s0 = up2(a0), s2 = up2(a2);
        float z = zc + ((s0.x + s0.y) + (s2.x + s2.y));
        if (t + 1 < T_) zc = g_XZ[(t + 1) * G4 + row];

        float a = (rr == 2) ? tanh_(z) : sigm(z);
        float af = __shfl_sync(0xffffffffu, a, base + 1);
        float ag = __shfl_sync(0xffffffffu, a, base + 2);
        float ao = __shfl_sync(0xffffffffu, a, base + 3);
        if (rr == 0) {
            c = fmaf(af, c, a * ag);
            hs[(t + 1) * H_ + j] = ao * tanh_(c);
        }
        __syncthreads();
    }

    const int o = tid & 63, tq = tid >> 6;
    u64 wm[32];
    {
        const float2* wr = (const float2*)(W1 + (size_t)o * FF + DI);
#pragma unroll
        for (int k = 0; k < 32; k++) { float2 v = wr[k]; wm[k] = pk2(v.x, v.y); }
    }
    const float b1v = b1[o];
    for (int t = tq; t < T_; t += 4) {
        const u64* h64 = (const u64*)(hs + (t + 1) * H_);
        u64 a0 = pk2(0.f, 0.f), a1 = a0, a2 = a0, a3 = a0;
#pragma unroll
        for (int k = 0; k < 32; k += 4) {
            a0 = ffma2(wm[k],     h64[k],     a0);
            a1 = ffma2(wm[k + 1], h64[k + 1], a1);
            a2 = ffma2(wm[k + 2], h64[k + 2], a2);
            a3 = ffma2(wm[k + 3], h64[k + 3], a3);
        }
        a0 = ffma2(one, a1, a0);
        a2 = ffma2(one, a3, a2);
        float2 s0 = up2(a0), s2 = up2(a2);
        g_macro1[t * DH + o] = ((s0.x + s0.y) + (s2.x + s2.y)) + b1v;
    }
}

// ---------- K4: warp-MMA fused MLP; layer2 A-operand via C->A register identity ----------
#define SM_XHI 0
#define SM_XLO 18432
#define SM_W1H 36864
#define SM_W1L 46080
#define SM_W2H 55296
#define SM_W2L 64512
#define SM_RAW 73728      // 4 warp slabs x 5888B
#define SM_WROW (SM_RAW + 23552)
#define SMEM_MLP (SM_WROW + 512)

// layer 1: 3-term fp16 split, A from smem (X)
__device__ __forceinline__ void do_layer1(
    uint32_t sb, const float* iv, float acc[2][8][4],
    int wid, int a_ro, int a_co, int b_ro, int b_co)
{
#pragma unroll
    for (int mi = 0; mi < 2; mi++)
#pragma unroll
        for (int ni = 0; ni < 8; ni++) {
            acc[mi][ni][0] = iv[2 * ni];
            acc[mi][ni][1] = iv[2 * ni + 1];
            acc[mi][ni][2] = iv[2 * ni];
            acc[mi][ni][3] = iv[2 * ni + 1];
        }
#pragma unroll
    for (int kc = 0; kc < 3; kc++) {
        uint32_t ah[2][4], al[2][4], bh[4][4], bl[4][4];
#pragma unroll
        for (int mi = 0; mi < 2; mi++) {
            uint32_t off = roff(wid * 32 + mi * 16 + a_ro, 2 * kc + a_co);
            ldsm4(ah[mi], sb + SM_XHI + off);
            ldsm4(al[mi], sb + SM_XLO + off);
        }
#pragma unroll
        for (int np = 0; np < 4; np++) {
            uint32_t off = roff(np * 16 + b_ro, 2 * kc + b_co);
            ldsm4(bh[np], sb + SM_W1H + off);
            ldsm4(bl[np], sb + SM_W1L + off);
        }
#pragma unroll
        for (int mi = 0; mi < 2; mi++)
#pragma unroll
            for (int ni = 0; ni < 8; ni++)
                mma16816(acc[mi][ni], ah[mi], &bh[ni >> 1][(ni & 1) * 2]);
#pragma unroll
        for (int mi = 0; mi < 2; mi++)
#pragma unroll
            for (int ni = 0; ni < 8; ni++)
                mma16816(acc[mi][ni], al[mi], &bh[ni >> 1][(ni & 1) * 2]);
#pragma unroll
        for (int mi = 0; mi < 2; mi++)
#pragma unroll
            for (int ni = 0; ni < 8; ni++)
                mma16816(acc[mi][ni], ah[mi], &bl[ni >> 1][(ni & 1) * 2]);
    }
}

__global__ void __launch_bounds__(128, 2)
k_mlp(const float* __restrict__ indiv, const unsigned char* __restrict__ mask_raw,
      const float* __restrict__ rets, const float* __restrict__ W1,
      const float* __restrict__ W2, const float* __restrict__ b2,
      const float* __restrict__ W3, const float* __restrict__ b3,
      float* __restrict__ out_w)
{
    extern __shared__ char sm[];
    const uint32_t sb = smem_u32(sm);
    float* wrow = (float*)(sm + SM_WROW);

    const int tid = threadIdx.x;
    const int wid = tid >> 5, lane = tid & 31;
    const int lq = lane & 7, qq = lane >> 3;
    const int a_ro = lq + ((qq & 1) << 3), a_co = qq >> 1;
    const int b_ro = lq + ((qq >> 1) << 3), b_co = qq & 1;
    const int cpair = (lane & 3) * 2;

    for (int idx = tid; idx < 64 * 64; idx += 128) {
        int n = idx >> 6, k = idx & 63;
        float v1 = (k < DI) ? W1[n * FF + k] : 0.f;
        float v2 = W2[idx];
        uint32_t o = roff(n, k >> 3) + (k & 7) * 2;
        __half h, l;
        split_hf(v1, h, l);
        *(__half*)(sm + SM_W1H + o) = h;
        *(__half*)(sm + SM_W1L + o) = l;
        split_hf(v2, h, l);
        *(__half*)(sm + SM_W2H + o) = h;
        *(__half*)(sm + SM_W2L + o) = l;
    }
    float b2v[16], w3v[16];
#pragma unroll
    for (int ni = 0; ni < 8; ni++) {
        b2v[2 * ni]     = b2[ni * 8 + cpair];
        b2v[2 * ni + 1] = b2[ni * 8 + cpair + 1];
        w3v[2 * ni]     = W3[ni * 8 + cpair];
        w3v[2 * ni + 1] = W3[ni * 8 + cpair + 1];
    }
    const float b3v = b3[0];
    const int mask_kind = g_mask_kind;
    __syncthreads();

    float acc[2][8][4];
    const uint32_t slab = sb + SM_RAW + wid * 5888;
    const float* rawf = (const float*)(sm + SM_RAW + wid * 5888);

    auto stage = [&](int tile) {
        const int t = tile >> 5;
        const int p0 = (tile & 31) * TILE;
        if ((p0 + wid * 32) < NN) {
            const float4* gsrc = (const float4*)(indiv + ((size_t)t * NN + p0 + wid * 32) * DI);
#pragma unroll
            for (int i = lane; i < 368; i += 32)
                cp16(slab + (uint32_t)i * 16, gsrc + i);
            asm volatile("cp.async.commit_group;" ::: "memory");
        }
    };

    if (blockIdx.x < NTILES) stage(blockIdx.x);

    for (int tile = blockIdx.x; tile < NTILES; tile += gridDim.x) {
        const int t = tile >> 5;
        const int p0 = (tile & 31) * TILE;
        const int pg = p0 + tid;
        const bool valid = pg < NN;

        float m1v[16];
#pragma unroll
        for (int ni = 0; ni < 8; ni++) {
            m1v[2 * ni]     = __ldg(&g_macro1[t * 64 + ni * 8 + cpair]);
            m1v[2 * ni + 1] = __ldg(&g_macro1[t * 64 + ni * 8 + cpair + 1]);
        }
        asm volatile("cp.async.wait_group 0;" ::: "memory");
        __syncwarp();

        // ---- split own row to fp16 hi/lo, swizzled STS ----
        {
            const float* rp = rawf + lane * DI;
            const uint32_t rbase = (uint32_t)(tid * 144);
            const int rot0 = tid >> 3;
#pragma unroll
            for (int c = 0; c < 6; c++) {
                uint32_t hw[4], lw[4];
#pragma unroll
                for (int jp = 0; jp < 4; jp++) {
                    int c0 = c * 8 + 2 * jp, c1 = c0 + 1;
                    float x0 = (c0 < DI) ? rp[c0] : 0.f;
                    float x1 = (c1 < DI) ? rp[c1] : 0.f;
                    __half h0, l0, h1, l1;
                    split_hf(x0, h0, l0);
                    split_hf(x1, h1, l1);
                    hw[jp] = pkhf(h0, h1);
                    lw[jp] = pkhf(l0, l1);
                }
                uint32_t off = rbase + (uint32_t)(((c + rot0) % 9) * 16);
                *(uint4*)(sm + SM_XHI + off) = make_uint4(hw[0], hw[1], hw[2], hw[3]);
                *(uint4*)(sm + SM_XLO + off) = make_uint4(lw[0], lw[1], lw[2], lw[3]);
            }
        }
        __syncwarp();

        // ---- layer 1: K=48 ----
        do_layer1(sb, m1v, acc, wid, a_ro, a_co, b_ro, b_co);

        // ---- prefetch NEXT tile's X into the (now dead) RAW slab ----
        {
            int nxt = tile + gridDim.x;
            if (nxt < NTILES) stage(nxt);
        }

        // ---- C->A register identity: relu + split layer-1 acc into layer-2 A frags ----
        uint32_t ah2[2][4][4], al2[2][4][4];
#pragma unroll
        for (int mi = 0; mi < 2; mi++)
#pragma unroll
            for (int kc = 0; kc < 4; kc++)
#pragma unroll
                for (int h2 = 0; h2 < 2; h2++) {
                    const int ni = 2 * kc + h2;
                    float r0 = fmaxf(acc[mi][ni][0], 0.f);
                    float r1 = fmaxf(acc[mi][ni][1], 0.f);
                    float r2 = fmaxf(acc[mi][ni][2], 0.f);
                    float r3 = fmaxf(acc[mi][ni][3], 0.f);
                    __half h0, l0, h1, l1, hh2, ll2, h3, l3;
                    split_hf(r0, h0, l0); split_hf(r1, h1, l1);
                    split_hf(r2, hh2, ll2); split_hf(r3, h3, l3);
                    ah2[mi][kc][2 * h2]     = pkhf(h0, h1);
                    ah2[mi][kc][2 * h2 + 1] = pkhf(hh2, h3);
                    al2[mi][kc][2 * h2]     = pkhf(l0, l1);
                    al2[mi][kc][2 * h2 + 1] = pkhf(ll2, l3);
                }

        // ---- layer 2 (A in registers) fused with W3 reduction ----
        float ws[4] = {0.f, 0.f, 0.f, 0.f};
#pragma unroll
        for (int np = 0; np < 4; np++) {
            float acc2[2][2][4];
#pragma unroll
            for (int mi = 0; mi < 2; mi++)
#pragma unroll
                for (int q = 0; q < 2; q++) {
                    const int ni = 2 * np + q;
                    acc2[mi][q][0] = b2v[2 * ni];
                    acc2[mi][q][1] = b2v[2 * ni + 1];
                    acc2[mi][q][2] = b2v[2 * ni];
                    acc2[mi][q][3] = b2v[2 * ni + 1];
                }
#pragma unroll
            for (int kc = 0; kc < 4; kc++) {
                uint32_t bh[4], bl[4];
                uint32_t off = roff(np * 16 + b_ro, 2 * kc + b_co);
                ldsm4(bh, sb + SM_W2H + off);
                ldsm4(bl, sb + SM_W2L + off);
#pragma unroll
                for (int mi = 0; mi < 2; mi++)
#pragma unroll
                    for (int q = 0; q < 2; q++) {
                        mma16816(acc2[mi][q], ah2[mi][kc], &bh[q * 2]);
                        mma16816(acc2[mi][q], al2[mi][kc], &bh[q * 2]);
                        mma16816(acc2[mi][q], ah2[mi][kc], &bl[q * 2]);
                    }
            }
#pragma unroll
            for (int mi = 0; mi < 2; mi++)
#pragma unroll
                for (int q = 0; q < 2; q++) {
                    const int ni = 2 * np + q;
                    ws[2 * mi]     = fmaf(w3v[2 * ni], fmaxf(acc2[mi][q][0], 0.f),
                                     fmaf(w3v[2 * ni + 1], fmaxf(acc2[mi][q][1], 0.f), ws[2 * mi]));
                    ws[2 * mi + 1] = fmaf(w3v[2 * ni], fmaxf(acc2[mi][q][2], 0.f),
                                     fmaf(w3v[2 * ni + 1], fmaxf(acc2[mi][q][3], 0.f), ws[2 * mi + 1]));
                }
        }

#pragma unroll
        for (int i = 0; i < 4; i++) {
            ws[i] += __shfl_xor_sync(0xffffffffu, ws[i], 1);
            ws[i] += __shfl_xor_sync(0xffffffffu, ws[i], 2);
        }
        float* wrowW = wrow + wid * 32;
        if ((lane & 3) == 0) {
            int r = lane >> 2;
            wrowW[r] = ws[0]; wrowW[r + 8] = ws[1];
            wrowW[r + 16] = ws[2]; wrowW[r + 24] = ws[3];
        }
        __syncwarp();

        // per-point finish
        float contrib = 0.f, mval = 0.f;
        {
            float w = wrowW[lane] + b3v;
            if (valid) {
                size_t gi = (size_t)t * NN + pg;
                float mf = (mask_kind == 0) ? (float)mask_raw[gi]
                         : (mask_kind == 1) ? (float)((const int*)mask_raw)[gi]
                         : ((const float*)mask_raw)[gi];
                float wm = w * mf;
                out_w[gi] = wm;
                contrib = wm * rets[gi];
                mval = mf;
            }
        }
#pragma unroll
        for (int off = 16; off; off >>= 1) {
            contrib += __shfl_down_sync(0xffffffffu, contrib, off);
            mval    += __shfl_down_sync(0xffffffffu, mval, off);
        }
        if (lane == 0) {
            atomicAdd(&g_sum[t], contrib);
            atomicAdd(&g_cnt[t], mval);
        }
    }
}

// ---------- K5: sdf finalize ----------
__global__ void __launch_bounds__(256) k_final(float* __restrict__ out_sdf) {
    __shared__ float smr[256];
    int t = threadIdx.x;
    float cnt = g_cnt[t];
    smr[t] = cnt;
    __syncthreads();
    for (int s = 128; s > 0; s >>= 1) {
        if (t < s) smr[t] += smr[t + s];
        __syncthreads();
    }
    float mean = smr[0] * (1.0f / 256.0f);
    out_sdf[t] = g_sum[t] / cnt * mean + 1.0f;
}

// ---------- launch ----------
extern "C" void kernel_launch(void* const* d_in, const int* in_sizes, int n_in,
                              void* d_out, int out_size) {
    (void)in_sizes; (void)n_in; (void)out_size;
    const float* macro = (const float*)d_in[0];
    const float* indiv = (const float*)d_in[1];
    const unsigned char* masks = (const unsigned char*)d_in[2];
    const float* rets  = (const float*)d_in[3];
    const float* W_ih  = (const float*)d_in[4];
    const float* W_hh  = (const float*)d_in[5];
    const float* b_ih  = (const float*)d_in[6];
    const float* b_hh  = (const float*)d_in[7];
    const float* W1    = (const float*)d_in[8];
    const float* b1    = (const float*)d_in[9];
    const float* W2    = (const float*)d_in[10];
    const float* b2    = (const float*)d_in[11];
    const float* W3    = (const float*)d_in[12];
    const float* b3    = (const float*)d_in[13];

    float* out     = (float*)d_out;
    float* out_sdf = out;          // sdf [T,1]
    float* out_w   = out + T_;     // weights [1,T,N,1]

    cudaFuncSetAttribute(k_prep, cudaFuncAttributeMaxDynamicSharedMemorySize, PREP_SMEM);
    cudaFuncSetAttribute(k_lstm, cudaFuncAttributeMaxDynamicSharedMemorySize, LSTM_SMEM);
    cudaFuncSetAttribute(k_mlp,  cudaFuncAttributeMaxDynamicSharedMemorySize, SMEM_MLP);

    k_prep<<<64, 256, PREP_SMEM>>>(macro, W_ih, b_ih, b_hh, masks);
    k_lstm<<<1, 256, LSTM_SMEM>>>(W_hh, W1, b1);
    k_mlp<<<GRID_MLP, 128, SMEM_MLP>>>(indiv, masks, rets, W1, W2, b2, W3, b3, out_w);
    k_final<<<1, T_>>>(out_sdf);
}

// round 12
// speedup vs baseline: 2.9231x; 1.0074x over previous
#include <cuda_runtime.h>
#include <cuda_fp16.h>
#include <cstdint>

#define T_  256
#define NN  4000
#define DM  178
#define DI  46
#define H_  64
#define DH  64
#define FF  110   // DI + H
#define G4  256   // 4*H
#define TILE 128
#define NTILES (T_ * 32)   // 8192
#define GRID_MLP 296

typedef unsigned long long u64;

// ---------- device scratch ----------
__device__ float g_XZ[T_ * G4];
__device__ float g_macro1[T_ * DH];
__device__ float g_sum[T_];
__device__ float g_cnt[T_];
__device__ int   g_mask_kind;   // 0=uint8/bool, 1=int32, 2=float32

// ---------- packed f32x2 helpers ----------
__device__ __forceinline__ u64 pk2(float lo, float hi) {
    u64 r; asm("mov.b64 %0, {%1, %2};" : "=l"(r) : "f"(lo), "f"(hi)); return r;
}
__device__ __forceinline__ u64 ffma2(u64 a, u64 b, u64 c) {
    u64 d; asm("fma.rn.f32x2 %0, %1, %2, %3;" : "=l"(d) : "l"(a), "l"(b), "l"(c)); return d;
}
__device__ __forceinline__ float2 up2(u64 a) {
    float2 f; asm("mov.b64 {%0, %1}, %2;" : "=f"(f.x), "=f"(f.y) : "l"(a)); return f;
}

// ---------- activations ----------
__device__ __forceinline__ float sigm(float x) {
    float e = exp2f(-1.44269504088896340736f * x);
    return __fdividef(1.0f, 1.0f + e);
}
__device__ __forceinline__ float tanh_(float x) {
    float a = fabsf(x);
    float e = exp2f(-2.88539008177792681472f * a);
    float r = __fdividef(1.0f - e, 1.0f + e);
    return copysignf(r, x);
}

// ---------- warp MMA helpers ----------
__device__ __forceinline__ uint32_t smem_u32(const void* p) {
    uint32_t a;
    asm("{ .reg .u64 t; cvta.to.shared.u64 t, %1; cvt.u32.u64 %0, t; }" : "=r"(a) : "l"(p));
    return a;
}
__device__ __forceinline__ void ldsm4(uint32_t* r, uint32_t addr) {
    asm volatile("ldmatrix.sync.aligned.m8n8.x4.shared.b16 {%0,%1,%2,%3}, [%4];"
        : "=r"(r[0]), "=r"(r[1]), "=r"(r[2]), "=r"(r[3]) : "r"(addr));
}
__device__ __forceinline__ void mma16816(float* d, const uint32_t* a, const uint32_t* b) {
    asm volatile("mma.sync.aligned.m16n8k16.row.col.f32.f16.f16.f32 "
        "{%0,%1,%2,%3}, {%4,%5,%6,%7}, {%8,%9}, {%0,%1,%2,%3};"
        : "+f"(d[0]), "+f"(d[1]), "+f"(d[2]), "+f"(d[3])
        : "r"(a[0]), "r"(a[1]), "r"(a[2]), "r"(a[3]), "r"(b[0]), "r"(b[1]));
}
__device__ __forceinline__ uint32_t pkhf(__half a, __half b) {
    return ((uint32_t)__half_as_ushort(b) << 16) | (uint32_t)__half_as_ushort(a);
}
__device__ __forceinline__ void split_hf(float x, __half& h, __half& l) {
    h = __float2half_rn(x);
    l = __float2half_rn(x - __half2float(h));
}
// row/chunk -> byte offset: 144B row stride, chunk rotation mod 9
__device__ __forceinline__ uint32_t roff(int r, int c) {
    return (uint32_t)(r * 144 + ((c + (r >> 3)) % 9) * 16);
}
__device__ __forceinline__ void cp16(uint32_t saddr, const void* gaddr) {
    asm volatile("cp.async.cg.shared.global [%0], [%1], 16;" :: "r"(saddr), "l"(gaddr));
}

// ---------- K1: XZ with smem-cached W slice (64 blocks) + mask detect ----------
#define PREP_SMEM ((64 * 185 + 16 * DM) * 4)
__global__ void __launch_bounds__(256) k_prep(const float* __restrict__ macro,
                                              const float* __restrict__ W_ih,
                                              const float* __restrict__ b_ih,
                                              const float* __restrict__ b_hh,
                                              const unsigned char* __restrict__ masks) {
    if (threadIdx.x == 0) cudaTriggerProgrammaticLaunchCompletion();
    extern __shared__ float psm[];
    float* Wsm = psm;                 // [64][185]
    float* xs  = psm + 64 * 185;      // [16][178]
    const int tid = threadIdx.x;
    const int gg = blockIdx.x & 3, tg = blockIdx.x >> 2;

    for (int idx = tid; idx < 64 * DM; idx += 256) {
        int g = idx / DM, k = idx - g * DM;
        Wsm[g * 185 + k] = W_ih[(size_t)(gg * 64 + g) * DM + k];
    }
    for (int idx = tid; idx < 16 * DM; idx += 256) {
        int tt = idx / DM, k = idx - tt * DM;
        xs[tt * DM + k] = macro[(size_t)(tg * 16 + tt) * DM + k];
    }
    if (gg == 0 && tid < 16) {
        g_sum[tg * 16 + tid] = 0.f;
        g_cnt[tg * 16 + tid] = 0.f;
    }
    __syncthreads();

    const int g = tid & 63, tq = tid >> 6;
    const float bsum = b_ih[gg * 64 + g] + b_hh[gg * 64 + g];
    const float* wrow = Wsm + g * 185;
    for (int tt = tq; tt < 16; tt += 4) {
        const float* xr = xs + tt * DM;
        float a0 = 0.f, a1 = 0.f, a2 = 0.f, a3 = 0.f;
#pragma unroll 4
        for (int k = 0; k < 176; k += 4) {
            a0 = fmaf(wrow[k],     xr[k],     a0);
            a1 = fmaf(wrow[k + 1], xr[k + 1], a1);
            a2 = fmaf(wrow[k + 2], xr[k + 2], a2);
            a3 = fmaf(wrow[k + 3], xr[k + 3], a3);
        }
        a0 = fmaf(wrow[176], xr[176], a0);
        a1 = fmaf(wrow[177], xr[177], a1);
        g_XZ[(tg * 16 + tt) * G4 + gg * 64 + g] = ((a0 + a1) + (a2 + a3)) + bsum;
    }

    if (blockIdx.x == 0) {
        __shared__ int s_any, s_flt;
        if (tid == 0) { s_any = 0; s_flt = 0; }
        __syncthreads();
        int ta = 0, tf = 0;
        for (int j = tid; j < 1024; j += 256) {
            unsigned char c1 = masks[4 * j + 1], c2 = masks[4 * j + 2], c3 = masks[4 * j + 3];
            if (c1 | c2 | c3) ta = 1;
            if (c3 == 0x3F) tf = 1;
        }
        if (ta) atomicOr(&s_any, 1);
        if (tf) atomicOr(&s_flt, 1);
        __syncthreads();
        if (tid == 0) g_mask_kind = s_flt ? 2 : (s_any ? 0 : 1);
    }
}

// ---------- K2: LSTM scan (2 gates/thread, 1 shfl + 1 bar per step) + fused macro1 ----------
// Active scan threads: tid<128 (warps 0-3). In each warp: lane<16 = role A (unit u = w*16+lane,
// rows i=u, g=128+u), lane>=16 = role B (unit u = w*16+lane-16, rows f=64+u, o=192+u).
#define LSTM_SMEM ((T_ + 1) * H_ * 4)
__global__ void __launch_bounds__(256, 1) k_lstm(const float* __restrict__ W_hh,
                                                 const float* __restrict__ W1,
                                                 const float* __restrict__ b1) {
    if (threadIdx.x == 0) cudaTriggerProgrammaticLaunchCompletion();
    extern __shared__ float hs[];
    const int tid = threadIdx.x;
    const int lane = tid & 31;
    const bool active = tid < 128;
    const bool roleA = (lane < 16);
    const int u = (tid >> 5) * 16 + (lane & 15);   // hidden unit (active threads)
    const int r0 = roleA ? u : (64 + u);            // i : f
    const int r1 = roleA ? (128 + u) : (192 + u);   // g : o

    // weights in registers (two gate rows, packed pairs)
    u64 w0[32], w1[32];
    if (active) {
        const float4* A = (const float4*)(W_hh + (size_t)r0 * H_);
        const float4* B = (const float4*)(W_hh + (size_t)r1 * H_);
#pragma unroll
        for (int k = 0; k < 16; k++) {
            float4 va = A[k], vb = B[k];
            w0[2 * k] = pk2(va.x, va.y); w0[2 * k + 1] = pk2(va.z, va.w);
            w1[2 * k] = pk2(vb.x, vb.y); w1[2 * k + 1] = pk2(vb.z, vb.w);
        }
    }
    if (tid < H_) hs[tid] = 0.f;   // h_{-1}

    cudaGridDependencySynchronize();   // g_XZ ready (k_prep complete)

    float c = 0.f;
    float z0 = active ? g_XZ[r0] : 0.f;
    float z1 = active ? g_XZ[r1] : 0.f;
    __syncthreads();

    const u64 one = pk2(1.f, 1.f);
    for (int t = 0; t < T_; t++) {
        if (active) {
            const u64* h64 = (const u64*)(hs + t * H_);
            u64 a0 = pk2(0.f, 0.f), a1 = a0, b0 = a0, b1a = a0;
#pragma unroll
            for (int k = 0; k < 32; k += 2) {
                a0  = ffma2(w0[k],     h64[k],     a0);
                a1  = ffma2(w0[k + 1], h64[k + 1], a1);
                b0  = ffma2(w1[k],     h64[k],     b0);
                b1a = ffma2(w1[k + 1], h64[k + 1], b1a);
            }
            a0 = ffma2(one, a1, a0);
            b0 = ffma2(one, b1a, b0);
            float2 sa = up2(a0), sb = up2(b0);
            float z0f = z0 + sa.x + sa.y;
            float z1f = z1 + sb.x + sb.y;
            if (t + 1 < T_) {
                z0 = g_XZ[(t + 1) * G4 + r0];
                z1 = g_XZ[(t + 1) * G4 + r1];
            }
            float p = 0.f;
            if (roleA) p = sigm(z0f) * tanh_(z1f);     // i*g
            p = __shfl_xor_sync(0xffffffffu, p, 16);   // deliver to role B
            if (!roleA) {
                float fv = sigm(z0f), ov = sigm(z1f);
                c = fmaf(fv, c, p);
                hs[(t + 1) * H_ + u] = ov * tanh_(c);
            }
        }
        __syncthreads();
    }

    // ---- fused macro1 (all 256 threads): m1[t][o] = b1[o] + W1[o][DI:] @ h_t ----
    const int o = tid & 63, tq = tid >> 6;
    u64 wm[32];
    {
        const float2* wr = (const float2*)(W1 + (size_t)o * FF + DI);
#pragma unroll
        for (int k = 0; k < 32; k++) { float2 v = wr[k]; wm[k] = pk2(v.x, v.y); }
    }
    const float b1v = b1[o];
    for (int t = tq; t < T_; t += 4) {
        const u64* h64 = (const u64*)(hs + (t + 1) * H_);
        u64 a0 = pk2(0.f, 0.f), a1 = a0, a2 = a0, a3 = a0;
#pragma unroll
        for (int k = 0; k < 32; k += 4) {
            a0 = ffma2(wm[k],     h64[k],     a0);
            a1 = ffma2(wm[k + 1], h64[k + 1], a1);
            a2 = ffma2(wm[k + 2], h64[k + 2], a2);
            a3 = ffma2(wm[k + 3], h64[k + 3], a3);
        }
        a0 = ffma2(one, a1, a0);
        a2 = ffma2(one, a3, a2);
        float2 s0 = up2(a0), s2 = up2(a2);
        g_macro1[t * DH + o] = ((s0.x + s0.y) + (s2.x + s2.y)) + b1v;
    }
}

// ---------- K4: warp-MMA fused MLP; layer2 A via C->A register identity ----------
#define SM_XHI 0
#define SM_XLO 18432
#define SM_W1H 36864
#define SM_W1L 46080
#define SM_W2H 55296
#define SM_W2L 64512
#define SM_RAW 73728      // 4 warp slabs x 5888B
#define SM_WROW (SM_RAW + 23552)
#define SMEM_MLP (SM_WROW + 512)

__device__ __forceinline__ void do_layer1(
    uint32_t sb, const float* iv, float acc[2][8][4],
    int wid, int a_ro, int a_co, int b_ro, int b_co)
{
#pragma unroll
    for (int mi = 0; mi < 2; mi++)
#pragma unroll
        for (int ni = 0; ni < 8; ni++) {
            acc[mi][ni][0] = iv[2 * ni];
            acc[mi][ni][1] = iv[2 * ni + 1];
            acc[mi][ni][2] = iv[2 * ni];
            acc[mi][ni][3] = iv[2 * ni + 1];
        }
#pragma unroll
    for (int kc = 0; kc < 3; kc++) {
        uint32_t ah[2][4], al[2][4], bh[4][4], bl[4][4];
#pragma unroll
        for (int mi = 0; mi < 2; mi++) {
            uint32_t off = roff(wid * 32 + mi * 16 + a_ro, 2 * kc + a_co);
            ldsm4(ah[mi], sb + SM_XHI + off);
            ldsm4(al[mi], sb + SM_XLO + off);
        }
#pragma unroll
        for (int np = 0; np < 4; np++) {
            uint32_t off = roff(np * 16 + b_ro, 2 * kc + b_co);
            ldsm4(bh[np], sb + SM_W1H + off);
            ldsm4(bl[np], sb + SM_W1L + off);
        }
#pragma unroll
        for (int mi = 0; mi < 2; mi++)
#pragma unroll
            for (int ni = 0; ni < 8; ni++)
                mma16816(acc[mi][ni], ah[mi], &bh[ni >> 1][(ni & 1) * 2]);
#pragma unroll
        for (int mi = 0; mi < 2; mi++)
#pragma unroll
            for (int ni = 0; ni < 8; ni++)
                mma16816(acc[mi][ni], al[mi], &bh[ni >> 1][(ni & 1) * 2]);
#pragma unroll
        for (int mi = 0; mi < 2; mi++)
#pragma unroll
            for (int ni = 0; ni < 8; ni++)
                mma16816(acc[mi][ni], ah[mi], &bl[ni >> 1][(ni & 1) * 2]);
    }
}

__global__ void __launch_bounds__(128, 2)
k_mlp(const float* __restrict__ indiv, const unsigned char* __restrict__ mask_raw,
      const float* __restrict__ rets, const float* __restrict__ W1,
      const float* __restrict__ W2, const float* __restrict__ b2,
      const float* __restrict__ W3, const float* __restrict__ b3,
      float* __restrict__ out_w)
{
    extern __shared__ char sm[];
    const uint32_t sb = smem_u32(sm);
    float* wrow = (float*)(sm + SM_WROW);

    const int tid = threadIdx.x;
    const int wid = tid >> 5, lane = tid & 31;
    const int lq = lane & 7, qq = lane >> 3;
    const int a_ro = lq + ((qq & 1) << 3), a_co = qq >> 1;
    const int b_ro = lq + ((qq >> 1) << 3), b_co = qq & 1;
    const int cpair = (lane & 3) * 2;

    // ---- preamble (independent of k_lstm output) ----
    for (int idx = tid; idx < 64 * 64; idx += 128) {
        int n = idx >> 6, k = idx & 63;
        float v1 = (k < DI) ? W1[n * FF + k] : 0.f;
        float v2 = W2[idx];
        uint32_t o = roff(n, k >> 3) + (k & 7) * 2;
        __half h, l;
        split_hf(v1, h, l);
        *(__half*)(sm + SM_W1H + o) = h;
        *(__half*)(sm + SM_W1L + o) = l;
        split_hf(v2, h, l);
        *(__half*)(sm + SM_W2H + o) = h;
        *(__half*)(sm + SM_W2L + o) = l;
    }
    float b2v[16], w3v[16];
#pragma unroll
    for (int ni = 0; ni < 8; ni++) {
        b2v[2 * ni]     = b2[ni * 8 + cpair];
        b2v[2 * ni + 1] = b2[ni * 8 + cpair + 1];
        w3v[2 * ni]     = W3[ni * 8 + cpair];
        w3v[2 * ni + 1] = W3[ni * 8 + cpair + 1];
    }
    const float b3v = b3[0];

    float acc[2][8][4];
    const uint32_t slab = sb + SM_RAW + wid * 5888;
    const float* rawf = (const float*)(sm + SM_RAW + wid * 5888);

    auto stage = [&](int tile) {
        const int t = tile >> 5;
        const int p0 = (tile & 31) * TILE;
        if ((p0 + wid * 32) < NN) {
            const float4* gsrc = (const float4*)(indiv + ((size_t)t * NN + p0 + wid * 32) * DI);
#pragma unroll
            for (int i = lane; i < 368; i += 32)
                cp16(slab + (uint32_t)i * 16, gsrc + i);
            asm volatile("cp.async.commit_group;" ::: "memory");
        }
    };

    if (blockIdx.x < NTILES) stage(blockIdx.x);
    __syncthreads();

    cudaGridDependencySynchronize();   // wait for k_lstm (and transitively k_prep)
    const int mask_kind = g_mask_kind;

    for (int tile = blockIdx.x; tile < NTILES; tile += gridDim.x) {
        const int t = tile >> 5;
        const int p0 = (tile & 31) * TILE;
        const int pg = p0 + tid;
        const bool valid = pg < NN;

        float m1v[16];
#pragma unroll
        for (int ni = 0; ni < 8; ni++) {
            m1v[2 * ni]     = __ldg(&g_macro1[t * 64 + ni * 8 + cpair]);
            m1v[2 * ni + 1] = __ldg(&g_macro1[t * 64 + ni * 8 + cpair + 1]);
        }
        asm volatile("cp.async.wait_group 0;" ::: "memory");
        __syncwarp();

        // ---- split own row to fp16 hi/lo, swizzled STS (float2 raw reads) ----
        {
            const float2* rp2 = (const float2*)(rawf + lane * DI);
            const uint32_t rbase = (uint32_t)(tid * 144);
            const int rot0 = tid >> 3;
#pragma unroll
            for (int c = 0; c < 6; c++) {
                uint32_t hw[4], lw[4];
#pragma unroll
                for (int jp = 0; jp < 4; jp++) {
                    int pi = c * 4 + jp;   // float2 pair index (0..23)
                    float2 v = (pi < 23) ? rp2[pi] : make_float2(0.f, 0.f);
                    if (!valid) v = make_float2(0.f, 0.f);
                    __half h0, l0, h1, l1;
                    split_hf(v.x, h0, l0);
                    split_hf(v.y, h1, l1);
                    hw[jp] = pkhf(h0, h1);
                    lw[jp] = pkhf(l0, l1);
                }
                uint32_t off = rbase + (uint32_t)(((c + rot0) % 9) * 16);
                *(uint4*)(sm + SM_XHI + off) = make_uint4(hw[0], hw[1], hw[2], hw[3]);
                *(uint4*)(sm + SM_XLO + off) = make_uint4(lw[0], lw[1], lw[2], lw[3]);
            }
        }
        __syncwarp();

        // ---- layer 1: K=48 ----
        do_layer1(sb, m1v, acc, wid, a_ro, a_co, b_ro, b_co);

        // ---- prefetch NEXT tile's X into the dead RAW slab ----
        {
            int nxt = tile + gridDim.x;
            if (nxt < NTILES) stage(nxt);
        }

        // ---- C->A register identity: relu + split layer-1 acc into layer-2 A frags ----
        uint32_t ah2[2][4][4], al2[2][4][4];
#pragma unroll
        for (int mi = 0; mi < 2; mi++)
#pragma unroll
            for (int kc = 0; kc < 4; kc++)
#pragma unroll
                for (int h2 = 0; h2 < 2; h2++) {
                    const int ni = 2 * kc + h2;
                    float r0 = fmaxf(acc[mi][ni][0], 0.f);
                    float r1 = fmaxf(acc[mi][ni][1], 0.f);
                    float r2 = fmaxf(acc[mi][ni][2], 0.f);
                    float r3 = fmaxf(acc[mi][ni][3], 0.f);
                    __half h0, l0, h1, l1, hh2, ll2, h3, l3;
                    split_hf(r0, h0, l0); split_hf(r1, h1, l1);
                    split_hf(r2, hh2, ll2); split_hf(r3, h3, l3);
                    ah2[mi][kc][2 * h2]     = pkhf(h0, h1);
                    ah2[mi][kc][2 * h2 + 1] = pkhf(hh2, h3);
                    al2[mi][kc][2 * h2]     = pkhf(l0, l1);
                    al2[mi][kc][2 * h2 + 1] = pkhf(ll2, l3);
                }

        // ---- layer 2 (A in registers) fused with W3 reduction ----
        float ws[4] = {0.f, 0.f, 0.f, 0.f};
#pragma unroll
        for (int np = 0; np < 4; np++) {
            float acc2[2][2][4];
#pragma unroll
            for (int mi = 0; mi < 2; mi++)
#pragma unroll
                for (int q = 0; q < 2; q++) {
                    const int ni = 2 * np + q;
                    acc2[mi][q][0] = b2v[2 * ni];
                    acc2[mi][q][1] = b2v[2 * ni + 1];
                    acc2[mi][q][2] = b2v[2 * ni];
                    acc2[mi][q][3] = b2v[2 * ni + 1];
                }
#pragma unroll
            for (int kc = 0; kc < 4; kc++) {
                uint32_t bh[4], bl[4];
                uint32_t off = roff(np * 16 + b_ro, 2 * kc + b_co);
                ldsm4(bh, sb + SM_W2H + off);
                ldsm4(bl, sb + SM_W2L + off);
#pragma unroll
                for (int mi = 0; mi < 2; mi++)
#pragma unroll
                    for (int q = 0; q < 2; q++) {
                        mma16816(acc2[mi][q], ah2[mi][kc], &bh[q * 2]);
                        mma16816(acc2[mi][q], al2[mi][kc], &bh[q * 2]);
                        mma16816(acc2[mi][q], ah2[mi][kc], &bl[q * 2]);
                    }
            }
#pragma unroll
            for (int mi = 0; mi < 2; mi++)
#pragma unroll
                for (int q = 0; q < 2; q++) {
                    const int ni = 2 * np + q;
                    ws[2 * mi]     = fmaf(w3v[2 * ni], fmaxf(acc2[mi][q][0], 0.f),
                                     fmaf(w3v[2 * ni + 1], fmaxf(acc2[mi][q][1], 0.f), ws[2 * mi]));
                    ws[2 * mi + 1] = fmaf(w3v[2 * ni], fmaxf(acc2[mi][q][2], 0.f),
                                     fmaf(w3v[2 * ni + 1], fmaxf(acc2[mi][q][3], 0.f), ws[2 * mi + 1]));
                }
        }

#pragma unroll
        for (int i = 0; i < 4; i++) {
            ws[i] += __shfl_xor_sync(0xffffffffu, ws[i], 1);
            ws[i] += __shfl_xor_sync(0xffffffffu, ws[i], 2);
        }
        float* wrowW = wrow + wid * 32;
        if ((lane & 3) == 0) {
            int r = lane >> 2;
            wrowW[r] = ws[0]; wrowW[r + 8] = ws[1];
            wrowW[r + 16] = ws[2]; wrowW[r + 24] = ws[3];
        }
        __syncwarp();

        // per-point finish
        float contrib = 0.f, mval = 0.f;
        {
            float w = wrowW[lane] + b3v;
            if (valid) {
                size_t gi = (size_t)t * NN + pg;
                float mf = (mask_kind == 0) ? (float)mask_raw[gi]
                         : (mask_kind == 1) ? (float)((const int*)mask_raw)[gi]
                         : ((const float*)mask_raw)[gi];
                float wm = w * mf;
                out_w[gi] = wm;
                contrib = wm * rets[gi];
                mval = mf;
            }
        }
#pragma unroll
        for (int off = 16; off; off >>= 1) {
            contrib += __shfl_down_sync(0xffffffffu, contrib, off);
            mval    += __shfl_down_sync(0xffffffffu, mval, off);
        }
        if (lane == 0) {
            atomicAdd(&g_sum[t], contrib);
            atomicAdd(&g_cnt[t], mval);
        }
    }
}

// ---------- K5: sdf finalize ----------
__global__ void __launch_bounds__(256) k_final(float* __restrict__ out_sdf) {
    __shared__ float smr[256];
    int t = threadIdx.x;
    float cnt = g_cnt[t];
    smr[t] = cnt;
    __syncthreads();
    for (int s = 128; s > 0; s >>= 1) {
        if (t < s) smr[t] += smr[t + s];
        __syncthreads();
    }
    float mean = smr[0] * (1.0f / 256.0f);
    out_sdf[t] = g_sum[t] / cnt * mean + 1.0f;
}

// ---------- launch ----------
extern "C" void kernel_launch(void* const* d_in, const int* in_sizes, int n_in,
                              void* d_out, int out_size) {
    (void)in_sizes; (void)n_in; (void)out_size;
    const float* macro = (const float*)d_in[0];
    const float* indiv = (const float*)d_in[1];
    const unsigned char* masks = (const unsigned char*)d_in[2];
    const float* rets  = (const float*)d_in[3];
    const float* W_ih  = (const float*)d_in[4];
    const float* W_hh  = (const float*)d_in[5];
    const float* b_ih  = (const float*)d_in[6];
    const float* b_hh  = (const float*)d_in[7];
    const float* W1    = (const float*)d_in[8];
    const float* b1    = (const float*)d_in[9];
    const float* W2    = (const float*)d_in[10];
    const float* b2    = (const float*)d_in[11];
    const float* W3    = (const float*)d_in[12];
    const float* b3    = (const float*)d_in[13];

    float* out     = (float*)d_out;
    float* out_sdf = out;          // sdf [T,1]
    float* out_w   = out + T_;     // weights [1,T,N,1]

    cudaFuncSetAttribute(k_prep, cudaFuncAttributeMaxDynamicSharedMemorySize, PREP_SMEM);
    cudaFuncSetAttribute(k_lstm, cudaFuncAttributeMaxDynamicSharedMemorySize, LSTM_SMEM);
    cudaFuncSetAttribute(k_mlp,  cudaFuncAttributeMaxDynamicSharedMemorySize, SMEM_MLP);

    // prep: plain launch
    k_prep<<<64, 256, PREP_SMEM>>>(macro, W_ih, b_ih, b_hh, masks);

    // lstm: PDL-dependent on prep
    {
        cudaLaunchConfig_t cfg = {};
        cfg.gridDim = dim3(1, 1, 1);
        cfg.blockDim = dim3(256, 1, 1);
        cfg.dynamicSmemBytes = LSTM_SMEM;
        cudaLaunchAttribute at[1];
        at[0].id = cudaLaunchAttributeProgrammaticStreamSerialization;
        at[0].val.programmaticStreamSerializationAllowed = 1;
        cfg.attrs = at;
        cfg.numAttrs = 1;
        cudaLaunchKernelEx(&cfg, k_lstm, W_hh, W1, b1);
    }

    // mlp: PDL-dependent on lstm
    {
        cudaLaunchConfig_t cfg = {};
        cfg.gridDim = dim3(GRID_MLP, 1, 1);
        cfg.blockDim = dim3(128, 1, 1);
        cfg.dynamicSmemBytes = SMEM_MLP;
        cudaLaunchAttribute at[1];
        at[0].id = cudaLaunchAttributeProgrammaticStreamSerialization;
        at[0].val.programmaticStreamSerializationAllowed = 1;
        cfg.attrs = at;
        cfg.numAttrs = 1;
        cudaLaunchKernelEx(&cfg, k_mlp, indiv, masks, rets, W1, W2, b2, W3, b3, out_w);
    }

    k_final<<<1, T_>>>(out_sdf);
}